// round 2
// baseline (speedup 1.0000x reference)
#include <cuda_runtime.h>
#include <math.h>

#define B_   8
#define H_   8
#define L_   1024
#define D_   64
#define DM_  512
#define RV_  65      // relative vocab (2*32+1)
#define QT   64      // queries per block
#define KT   64      // keys per chunk
#define NCHUNK (L_/KT)

// -------- scratch (device globals; no runtime allocation allowed) --------
__device__ float g_q[B_*H_*L_*D_];      // scaled q, [b,h,l,d]
__device__ float g_k[B_*H_*L_*D_];
__device__ float g_v[B_*H_*L_*D_];
__device__ float g_qrel[B_*H_*L_*RV_];  // q . rel_emb_k[r]
__device__ float g_ctx[B_*L_*DM_];      // attention output, [b*l, h*64+d]

// ============================ GEMM (M=8192,K=512,N=512) ============================
// MODE 0: C = g_ctx @ W + bias            -> Cout row-major [m][n]
// MODE 1: C = (A @ W + bias)*scale        -> g_q in [b,h,l,d]
// MODE 2/3: same                          -> g_k / g_v
template<int MODE>
__global__ void __launch_bounds__(256) gemm512_kernel(
    const float* __restrict__ A, const float* __restrict__ W,
    const float* __restrict__ bias, float* __restrict__ Cout, float scale)
{
    __shared__ __align__(16) float As[16][64];   // [k][m]
    __shared__ __align__(16) float Ws[16][64];   // [k][n]
    const int tid = threadIdx.x;
    const int bm = blockIdx.x * 64;
    const int bn = blockIdx.y * 64;
    const int tx = tid & 15, ty = tid >> 4;
    const int lm  = tid >> 2,        lk4 = (tid & 3) << 2;   // A tile load
    const int wk  = tid >> 4,        wn4 = (tid & 15) << 2;  // W tile load
    const float* Ap = (MODE == 0) ? g_ctx : A;

    float acc[4][4] = {};
    for (int k0 = 0; k0 < DM_; k0 += 16) {
        float4 a4 = *(const float4*)(Ap + (size_t)(bm + lm) * DM_ + k0 + lk4);
        As[lk4+0][lm] = a4.x; As[lk4+1][lm] = a4.y;
        As[lk4+2][lm] = a4.z; As[lk4+3][lm] = a4.w;
        *(float4*)&Ws[wk][wn4] = *(const float4*)(W + (size_t)(k0 + wk) * DM_ + bn + wn4);
        __syncthreads();
#pragma unroll
        for (int kk = 0; kk < 16; kk++) {
            float4 av = *(const float4*)&As[kk][ty << 2];
            float4 bv = *(const float4*)&Ws[kk][tx << 2];
            float aa[4] = {av.x, av.y, av.z, av.w};
            float bb[4] = {bv.x, bv.y, bv.z, bv.w};
#pragma unroll
            for (int i = 0; i < 4; i++)
#pragma unroll
                for (int j = 0; j < 4; j++)
                    acc[i][j] += aa[i] * bb[j];
        }
        __syncthreads();
    }
#pragma unroll
    for (int i = 0; i < 4; i++) {
        const int m = bm + (ty << 2) + i;
#pragma unroll
        for (int j = 0; j < 4; j++) {
            const int n = bn + (tx << 2) + j;
            float val = (acc[i][j] + bias[n]) * scale;
            if (MODE == 0) {
                Cout[(size_t)m * DM_ + n] = val;
            } else {
                const int b = m >> 10, l = m & 1023;
                const int h = n >> 6,  d = n & 63;
                float* dst = (MODE == 1) ? g_q : (MODE == 2) ? g_k : g_v;
                dst[(size_t)((b * H_ + h) * L_ + l) * D_ + d] = val;
            }
        }
    }
}

// ============================ qrel: [rows=BHL] x [65] ============================
__global__ void __launch_bounds__(256) qrel_kernel(const float* __restrict__ rel_emb_k)
{
    __shared__ __align__(16) float qs[16][D_];      // declared FIRST + aligned
    __shared__ __align__(16) float emb[RV_][RV_];   // [r][d], stride 65 -> conflict-free
    const int tid = threadIdx.x;
    const int row0 = blockIdx.x * 16;

    for (int e = tid; e < RV_ * D_; e += 256)
        emb[e / D_][e % D_] = rel_emb_k[e];
    {
        const int e = tid * 4; // exactly 1024 elements
        *(float4*)&qs[0][e] = *(const float4*)(g_q + (size_t)row0 * D_ + e);
    }
    __syncthreads();

    const int lr = tid >> 4;     // local row 0..15
    const int r0 = tid & 15;
    for (int r = r0; r < RV_; r += 16) {
        float s = 0.f;
#pragma unroll
        for (int d = 0; d < D_; d++) s += qs[lr][d] * emb[r][d];
        g_qrel[(size_t)(row0 + lr) * RV_ + r] = s;
    }
}

// ============================ fused attention ============================
struct __align__(16) AttnSmem {
    float Qs[QT][D_];        // q tile
    float QRs[QT][RV_];      // qrel tile  (65*4=260B rows; total multiple of 16)
    float Ks[KT][65];        // key chunk (padded 65 -> conflict-free strided reads)
    float Vs[KT][D_];        // value chunk
    float S[QT][66];         // scores / probabilities
    float bucket[QT][RV_];   // attention mass per relative bucket
    float relv[RV_][D_];     // rel_emb_v
    float red[QT][4];
    float redlo[QT][4];
    float redhi[QT][4];
    float mrow[QT], lrow[QT], alpha_s[QT];
    float treecol[64];       // tree_emb[:, h]
};

__global__ void __launch_bounds__(256, 1) attn_kernel(
    const int* __restrict__ rel_matrix, const float* __restrict__ rel_mask,
    const unsigned char* __restrict__ mask, const float* __restrict__ tree_emb,
    const float* __restrict__ rel_emb_v)
{
    extern __shared__ __align__(16) char smraw[];
    AttnSmem& sm = *reinterpret_cast<AttnSmem*>(smraw);

    const int tid   = threadIdx.x;
    const int h     = blockIdx.y;
    const int b     = blockIdx.z;
    const int qbase = blockIdx.x * QT;
    const int bh    = b * H_ + h;

    // ---- stage-in ----
    const float* qtile = g_q + (size_t)(bh * L_ + qbase) * D_;
    for (int e = tid * 4; e < QT * D_; e += 1024)
        *(float4*)&sm.Qs[0][e] = *(const float4*)&qtile[e];
    {
        const float* qr = g_qrel + (size_t)(bh * L_ + qbase) * RV_;
        for (int e = tid; e < QT * RV_; e += 256) sm.QRs[0][e] = qr[e];
    }
    for (int e = tid * 4; e < RV_ * D_; e += 1024)
        *(float4*)&sm.relv[0][e] = *(const float4*)&rel_emb_v[e];
    if (tid < 64) sm.treecol[tid] = tree_emb[tid * H_ + h];
    if (tid < QT) { sm.mrow[tid] = -1e30f; sm.lrow[tid] = 0.f; }
    for (int e = tid; e < QT * RV_; e += 256) sm.bucket[0][e] = 0.f;

    const int q0 = (tid >> 4) << 2;       // 0,4,...,60 (shared by QK/AV/epilogue)
    const int kl = tid & 15;              // QK key lanes: k = kl + 16*j
    const int d0 = (tid & 15) << 2;       // AV dim group
    float oacc[4][4] = {};

    __syncthreads();

    for (int c = 0; c < NCHUNK; c++) {
        const int kb = c * KT;
        // ---- load K (stride 65) and V ----
        const float* ktile = g_k + (size_t)(bh * L_ + kb) * D_;
        const float* vtile = g_v + (size_t)(bh * L_ + kb) * D_;
        for (int e = tid * 4; e < KT * D_; e += 1024) {
            float4 kv = *(const float4*)&ktile[e];
            const int kk = e >> 6, dd = e & 63;
            sm.Ks[kk][dd+0] = kv.x; sm.Ks[kk][dd+1] = kv.y;
            sm.Ks[kk][dd+2] = kv.z; sm.Ks[kk][dd+3] = kv.w;
            *(float4*)&sm.Vs[0][e] = *(const float4*)&vtile[e];
        }
        __syncthreads();

        // ---- QK^T: 4q x 4k per thread ----
        {
            float sacc[4][4] = {};
#pragma unroll 16
            for (int d = 0; d < D_; d++) {
                float a0 = sm.Qs[q0+0][d], a1 = sm.Qs[q0+1][d];
                float a2 = sm.Qs[q0+2][d], a3 = sm.Qs[q0+3][d];
                float b0 = sm.Ks[kl+ 0][d], b1 = sm.Ks[kl+16][d];
                float b2 = sm.Ks[kl+32][d], b3 = sm.Ks[kl+48][d];
                sacc[0][0]+=a0*b0; sacc[0][1]+=a0*b1; sacc[0][2]+=a0*b2; sacc[0][3]+=a0*b3;
                sacc[1][0]+=a1*b0; sacc[1][1]+=a1*b1; sacc[1][2]+=a1*b2; sacc[1][3]+=a1*b3;
                sacc[2][0]+=a2*b0; sacc[2][1]+=a2*b1; sacc[2][2]+=a2*b2; sacc[2][3]+=a2*b3;
                sacc[3][0]+=a3*b0; sacc[3][1]+=a3*b1; sacc[3][2]+=a3*b2; sacc[3][3]+=a3*b3;
            }
#pragma unroll
            for (int i = 0; i < 4; i++)
#pragma unroll
                for (int j = 0; j < 4; j++)
                    sm.S[q0+i][kl + 16*j] = sacc[i][j];
        }
        __syncthreads();

        // ---- bias + mask (coalesced along k) ----
        {
            const int kk2 = tid & 63;
            const int qq0 = tid >> 6;
            const int kg  = kb + kk2;
#pragma unroll
            for (int i = 0; i < 16; i++) {
                const int qq = qq0 + i * 4;
                const int qg = qbase + qq;
                const size_t idx = (size_t)(b * L_ + qg) * L_ + kg;
                const int rm = rel_matrix[idx];
                const float rmk = rel_mask[idx];
                const unsigned char mk = mask[idx];
                int r = kg - qg; r = max(-32, min(32, r)) + 32;
                float sv = sm.S[qq][kk2] + sm.QRs[qq][r] + sm.treecol[rm] * rmk;
                sm.S[qq][kk2] = mk ? -1e18f : sv;
            }
        }
        __syncthreads();

        // ---- online softmax: chunk max ----
        {
            const int qr = tid & 63, sl = tid >> 6;
            float pm = -1e30f;
#pragma unroll
            for (int j = 0; j < 16; j++) pm = fmaxf(pm, sm.S[qr][sl*16 + j]);
            sm.red[qr][sl] = pm;
        }
        __syncthreads();
        if (tid < QT) {
            const float mo = sm.mrow[tid];
            float mn = fmaxf(fmaxf(sm.red[tid][0], sm.red[tid][1]),
                             fmaxf(sm.red[tid][2], sm.red[tid][3]));
            mn = fmaxf(mo, mn);
            sm.mrow[tid]    = mn;
            sm.alpha_s[tid] = __expf(mo - mn);
        }
        __syncthreads();

        // ---- rescale running state by alpha ----
        for (int e = tid; e < QT * RV_; e += 256) sm.bucket[0][e] *= sm.alpha_s[e / RV_];
        if (tid < QT) sm.lrow[tid] *= sm.alpha_s[tid];
#pragma unroll
        for (int i = 0; i < 4; i++) {
            const float al = sm.alpha_s[q0 + i];
#pragma unroll
            for (int j = 0; j < 4; j++) oacc[i][j] *= al;
        }
        __syncthreads();

        // ---- exp + bucket accumulation ----
        {
            const int qr = tid & 63, sl = tid >> 6;
            const int qg = qbase + qr;
            const float mq = sm.mrow[qr];
            float lsum = 0.f, lo = 0.f, hi = 0.f;
#pragma unroll
            for (int j = 0; j < 16; j++) {
                const int kk2 = sl * 16 + j;
                float p = __expf(sm.S[qr][kk2] - mq);
                sm.S[qr][kk2] = p;
                lsum += p;
                const int rd = kb + kk2 - qg;
                if (rd <= -32)      lo += p;
                else if (rd >= 32)  hi += p;
                else                sm.bucket[qr][rd + 32] += p;  // unique (q,r) per thread
            }
            sm.red[qr][sl] = lsum; sm.redlo[qr][sl] = lo; sm.redhi[qr][sl] = hi;
        }
        __syncthreads();
        if (tid < QT) {
            sm.lrow[tid] += sm.red[tid][0] + sm.red[tid][1] + sm.red[tid][2] + sm.red[tid][3];
            sm.bucket[tid][0]     += sm.redlo[tid][0] + sm.redlo[tid][1] + sm.redlo[tid][2] + sm.redlo[tid][3];
            sm.bucket[tid][RV_-1] += sm.redhi[tid][0] + sm.redhi[tid][1] + sm.redhi[tid][2] + sm.redhi[tid][3];
        }
        __syncthreads();

        // ---- P @ V: 4q x 4d per thread ----
        {
#pragma unroll 8
            for (int kk = 0; kk < KT; kk++) {
                float4 vv = *(const float4*)&sm.Vs[kk][d0];
                float p0 = sm.S[q0+0][kk], p1 = sm.S[q0+1][kk];
                float p2 = sm.S[q0+2][kk], p3 = sm.S[q0+3][kk];
                oacc[0][0]+=p0*vv.x; oacc[0][1]+=p0*vv.y; oacc[0][2]+=p0*vv.z; oacc[0][3]+=p0*vv.w;
                oacc[1][0]+=p1*vv.x; oacc[1][1]+=p1*vv.y; oacc[1][2]+=p1*vv.z; oacc[1][3]+=p1*vv.w;
                oacc[2][0]+=p2*vv.x; oacc[2][1]+=p2*vv.y; oacc[2][2]+=p2*vv.z; oacc[2][3]+=p2*vv.w;
                oacc[3][0]+=p3*vv.x; oacc[3][1]+=p3*vv.y; oacc[3][2]+=p3*vv.z; oacc[3][3]+=p3*vv.w;
            }
        }
        __syncthreads();
    }

    // ---- rel_v context from buckets: oacc += bucket @ rel_emb_v ----
#pragma unroll 5
    for (int r = 0; r < RV_; r++) {
        float4 rv = *(const float4*)&sm.relv[r][d0];
        float b0 = sm.bucket[q0+0][r], b1 = sm.bucket[q0+1][r];
        float b2 = sm.bucket[q0+2][r], b3 = sm.bucket[q0+3][r];
        oacc[0][0]+=b0*rv.x; oacc[0][1]+=b0*rv.y; oacc[0][2]+=b0*rv.z; oacc[0][3]+=b0*rv.w;
        oacc[1][0]+=b1*rv.x; oacc[1][1]+=b1*rv.y; oacc[1][2]+=b1*rv.z; oacc[1][3]+=b1*rv.w;
        oacc[2][0]+=b2*rv.x; oacc[2][1]+=b2*rv.y; oacc[2][2]+=b2*rv.z; oacc[2][3]+=b2*rv.w;
        oacc[3][0]+=b3*rv.x; oacc[3][1]+=b3*rv.y; oacc[3][2]+=b3*rv.z; oacc[3][3]+=b3*rv.w;
    }

    // ---- normalize + write ctx [b*l, h*64+d] ----
#pragma unroll
    for (int i = 0; i < 4; i++) {
        const float inv = 1.0f / sm.lrow[q0 + i];
        float4 o;
        o.x = oacc[i][0] * inv; o.y = oacc[i][1] * inv;
        o.z = oacc[i][2] * inv; o.w = oacc[i][3] * inv;
        *(float4*)&g_ctx[(size_t)(b * L_ + qbase + q0 + i) * DM_ + h * D_ + d0] = o;
    }
}

// ============================ launch ============================
extern "C" void kernel_launch(void* const* d_in, const int* in_sizes, int n_in,
                              void* d_out, int out_size)
{
    const float* key        = (const float*)d_in[0];
    const float* value      = (const float*)d_in[1];
    const float* query      = (const float*)d_in[2];
    const unsigned char* mask = (const unsigned char*)d_in[3];
    const int*   rel_matrix = (const int*)d_in[4];
    const float* rel_mask   = (const float*)d_in[5];
    const float* Wk = (const float*)d_in[6];
    const float* bk = (const float*)d_in[7];
    const float* Wq = (const float*)d_in[8];
    const float* bq = (const float*)d_in[9];
    const float* Wv = (const float*)d_in[10];
    const float* bv = (const float*)d_in[11];
    const float* Wo = (const float*)d_in[12];
    const float* bo = (const float*)d_in[13];
    const float* rel_emb_k  = (const float*)d_in[14];
    const float* rel_emb_v  = (const float*)d_in[15];
    const float* tree_emb   = (const float*)d_in[16];

    static bool attr_set = false;
    if (!attr_set) {
        cudaFuncSetAttribute(attn_kernel, cudaFuncAttributeMaxDynamicSharedMemorySize,
                             (int)sizeof(AttnSmem));
        attr_set = true;
    }

    dim3 gemm_grid(B_ * L_ / 64, DM_ / 64);              // (128, 8)

    gemm512_kernel<1><<<gemm_grid, 256>>>(query, Wq, bq, nullptr, 0.125f); // q scaled by 1/sqrt(64)
    gemm512_kernel<2><<<gemm_grid, 256>>>(key,   Wk, bk, nullptr, 1.0f);
    gemm512_kernel<3><<<gemm_grid, 256>>>(value, Wv, bv, nullptr, 1.0f);

    qrel_kernel<<<(B_ * H_ * L_) / 16, 256>>>(rel_emb_k);

    attn_kernel<<<dim3(L_ / QT, H_, B_), 256, sizeof(AttnSmem)>>>(
        rel_matrix, rel_mask, mask, tree_emb, rel_emb_v);

    gemm512_kernel<0><<<gemm_grid, 256>>>(nullptr, Wo, bo, (float*)d_out, 1.0f);
}

// round 3
// speedup vs baseline: 1.1460x; 1.1460x over previous
#include <cuda_runtime.h>
#include <math.h>

#define B_   8
#define H_   8
#define L_   1024
#define D_   64
#define DM_  512
#define RV_  65      // relative vocab (2*32+1)
#define QT   64      // queries per block
#define KT   64      // keys per chunk
#define NCHUNK (L_/KT)

// -------- scratch (device globals; no runtime allocation allowed) --------
__device__ float g_q[B_*H_*L_*D_];      // scaled q, [b,h,l,d]
__device__ float g_k[B_*H_*L_*D_];
__device__ float g_v[B_*H_*L_*D_];
__device__ float g_qrel[B_*H_*L_*RV_];  // q . rel_emb_k[r]
__device__ float g_ctx[B_*L_*DM_];      // attention output, [b*l, h*64+d]

// ---------------- fast exp: FMA pipe instead of MUFU ----------------
// exp(x) = 2^(x*log2e); 2^f via degree-5 Taylor in ln2 on f in [-0.5,0.5],
// integer part folded into the exponent bits. rel err ~2e-6.
__device__ __forceinline__ float fast_exp(float x) {
    x = fmaxf(x, -80.0f);                       // keep exponent math in range
    float t = x * 1.4426950408889634f;
    int   e = __float2int_rn(t);
    float f = t - (float)e;
    float p = 1.3333558146428443e-3f;
    p = fmaf(p, f, 9.6181291976983960e-3f);
    p = fmaf(p, f, 5.5504108664821580e-2f);
    p = fmaf(p, f, 2.4022650695910071e-1f);
    p = fmaf(p, f, 6.9314718055994531e-1f);
    p = fmaf(p, f, 1.0f);
    return __int_as_float(__float_as_int(p) + (e << 23));
}

// ---------------- tf32 helpers ----------------
__device__ __forceinline__ unsigned f2tf(float x) {
    unsigned r;
    asm("cvt.rna.tf32.f32 %0, %1;" : "=r"(r) : "f"(x));
    return r;
}
__device__ __forceinline__ void mma_tf32(float c[4], const unsigned a[4], const unsigned b[2]) {
    asm volatile("mma.sync.aligned.m16n8k8.row.col.f32.tf32.tf32.f32 "
        "{%0,%1,%2,%3}, {%4,%5,%6,%7}, {%8,%9}, {%0,%1,%2,%3};\n"
        : "+f"(c[0]), "+f"(c[1]), "+f"(c[2]), "+f"(c[3])
        : "r"(a[0]), "r"(a[1]), "r"(a[2]), "r"(a[3]), "r"(b[0]), "r"(b[1]));
}

// ============================ tensor-core GEMM (M=8192,K=512,N=512) ============================
// MODE 0: C = g_ctx @ W + bias                -> Cout row-major [m][n]
// MODE 1/2/3: C = (A @ W + bias)*scale        -> g_q / g_k / g_v in [b,h,l,d]
// Block tile 128x64, 8 warps (4m x 2n), warp tile 32x32, k-tile 32, tf32 mma m16n8k8.
template<int MODE>
__global__ void __launch_bounds__(256) gemm_tc(
    const float* __restrict__ Ain, const float* __restrict__ W,
    const float* __restrict__ bias, float* __restrict__ Cout, float scale)
{
    __shared__ __align__(16) unsigned As[128][36];   // [m][k], pad->conflict-free frags
    __shared__ __align__(16) unsigned Bs[32][68];    // [k][n], pad 4
    const int tid  = threadIdx.x;
    const int lane = tid & 31;
    const int wid  = tid >> 5;
    const int bm = blockIdx.x * 128, bn = blockIdx.y * 64;
    const int wm = (wid & 3) << 5;
    const int wn = (wid >> 2) << 5;
    const float* Ap = (MODE == 0) ? g_ctx : Ain;

    const int arow = tid >> 1;            // 0..127
    const int acol = (tid & 1) << 4;      // 0 / 16
    const int brow = tid >> 3;            // 0..31
    const int bcol = (tid & 7) << 3;      // 0..56

    const float* aptr = Ap + (size_t)(bm + arow) * DM_ + acol;

    float4 ra[4], rb[2];
#pragma unroll
    for (int i = 0; i < 4; i++) ra[i] = *(const float4*)(aptr + i * 4);
#pragma unroll
    for (int i = 0; i < 2; i++)
        rb[i] = *(const float4*)(W + (size_t)brow * DM_ + bn + bcol + i * 4);

    float c[2][4][4] = {};
    const int g = lane >> 2, q = lane & 3;

    for (int kt = 0; kt < DM_; kt += 32) {
        // stage current tile to smem (convert to tf32 bits)
#pragma unroll
        for (int i = 0; i < 4; i++) {
            As[arow][acol + i*4 + 0] = f2tf(ra[i].x);
            As[arow][acol + i*4 + 1] = f2tf(ra[i].y);
            As[arow][acol + i*4 + 2] = f2tf(ra[i].z);
            As[arow][acol + i*4 + 3] = f2tf(ra[i].w);
        }
#pragma unroll
        for (int i = 0; i < 2; i++) {
            Bs[brow][bcol + i*4 + 0] = f2tf(rb[i].x);
            Bs[brow][bcol + i*4 + 1] = f2tf(rb[i].y);
            Bs[brow][bcol + i*4 + 2] = f2tf(rb[i].z);
            Bs[brow][bcol + i*4 + 3] = f2tf(rb[i].w);
        }
        __syncthreads();

        // prefetch next tile (hide DRAM latency behind mma)
        if (kt + 32 < DM_) {
#pragma unroll
            for (int i = 0; i < 4; i++) ra[i] = *(const float4*)(aptr + kt + 32 + i * 4);
#pragma unroll
            for (int i = 0; i < 2; i++)
                rb[i] = *(const float4*)(W + (size_t)(kt + 32 + brow) * DM_ + bn + bcol + i * 4);
        }

#pragma unroll
        for (int ks = 0; ks < 32; ks += 8) {
            unsigned a[2][4], b[4][2];
#pragma unroll
            for (int mi = 0; mi < 2; mi++) {
                const int r = wm + (mi << 4) + g;
                a[mi][0] = As[r    ][ks + q    ];
                a[mi][1] = As[r + 8][ks + q    ];
                a[mi][2] = As[r    ][ks + q + 4];
                a[mi][3] = As[r + 8][ks + q + 4];
            }
#pragma unroll
            for (int ni = 0; ni < 4; ni++) {
                b[ni][0] = Bs[ks + q    ][wn + (ni << 3) + g];
                b[ni][1] = Bs[ks + q + 4][wn + (ni << 3) + g];
            }
#pragma unroll
            for (int mi = 0; mi < 2; mi++)
#pragma unroll
                for (int ni = 0; ni < 4; ni++)
                    mma_tf32(c[mi][ni], a[mi], b[ni]);
        }
        __syncthreads();
    }

    // epilogue
#pragma unroll
    for (int mi = 0; mi < 2; mi++) {
#pragma unroll
        for (int ni = 0; ni < 4; ni++) {
            const int n0 = bn + wn + (ni << 3) + (q << 1);
            const float b0 = bias[n0], b1 = bias[n0 + 1];
#pragma unroll
            for (int hh = 0; hh < 2; hh++) {
                const int m = bm + wm + (mi << 4) + g + hh * 8;
                float2 o;
                o.x = (c[mi][ni][hh*2 + 0] + b0) * scale;
                o.y = (c[mi][ni][hh*2 + 1] + b1) * scale;
                if (MODE == 0) {
                    *(float2*)&Cout[(size_t)m * DM_ + n0] = o;
                } else {
                    const int b = m >> 10, l = m & 1023;
                    const int h = n0 >> 6, d = n0 & 63;
                    float* dst = (MODE == 1) ? g_q : (MODE == 2) ? g_k : g_v;
                    *(float2*)&dst[(size_t)((b * H_ + h) * L_ + l) * D_ + d] = o;
                }
            }
        }
    }
}

// ============================ qrel: [rows=BHL] x [65] ============================
__global__ void __launch_bounds__(256) qrel_kernel(const float* __restrict__ rel_emb_k)
{
    __shared__ __align__(16) float qs[16][D_];
    __shared__ __align__(16) float emb[RV_][RV_];   // [r][d], stride 65 -> conflict-free
    const int tid = threadIdx.x;
    const int row0 = blockIdx.x * 16;

    for (int e = tid; e < RV_ * D_; e += 256)
        emb[e / D_][e % D_] = rel_emb_k[e];
    {
        const int e = tid * 4; // exactly 1024 elements
        *(float4*)&qs[0][e] = *(const float4*)(g_q + (size_t)row0 * D_ + e);
    }
    __syncthreads();

    const int lr = tid >> 4;     // local row 0..15
    const int r0 = tid & 15;
    for (int r = r0; r < RV_; r += 16) {
        float s = 0.f;
#pragma unroll
        for (int d = 0; d < D_; d++) s += qs[lr][d] * emb[r][d];
        g_qrel[(size_t)(row0 + lr) * RV_ + r] = s;
    }
}

// ============================ fused attention ============================
struct __align__(16) AttnSmem {
    float Qs[QT][D_];        // q tile
    float QRs[QT][RV_];      // qrel tile
    float Ks[KT][65];        // key chunk (padded 65 -> conflict-free strided reads)
    float Vs[KT][D_];        // value chunk
    float S[QT][66];         // scores / probabilities
    float bucket[QT][RV_];   // attention mass per relative bucket
    float relv[RV_][D_];     // rel_emb_v
    float red[QT][4];
    float redlo[QT][4];
    float redhi[QT][4];
    float mrow[QT], lrow[QT], alpha_s[QT];
    float treecol[64];       // tree_emb[:, h]
};

__global__ void __launch_bounds__(256, 1) attn_kernel(
    const int* __restrict__ rel_matrix, const float* __restrict__ rel_mask,
    const unsigned char* __restrict__ mask, const float* __restrict__ tree_emb,
    const float* __restrict__ rel_emb_v)
{
    extern __shared__ __align__(16) char smraw[];
    AttnSmem& sm = *reinterpret_cast<AttnSmem*>(smraw);

    const int tid   = threadIdx.x;
    const int h     = blockIdx.y;
    const int b     = blockIdx.z;
    const int qbase = blockIdx.x * QT;
    const int bh    = b * H_ + h;

    // ---- stage-in ----
    const float* qtile = g_q + (size_t)(bh * L_ + qbase) * D_;
    for (int e = tid * 4; e < QT * D_; e += 1024)
        *(float4*)&sm.Qs[0][e] = *(const float4*)&qtile[e];
    {
        const float* qr = g_qrel + (size_t)(bh * L_ + qbase) * RV_;
        for (int e = tid; e < QT * RV_; e += 256) sm.QRs[0][e] = qr[e];
    }
    for (int e = tid * 4; e < RV_ * D_; e += 1024)
        *(float4*)&sm.relv[0][e] = *(const float4*)&rel_emb_v[e];
    if (tid < 64) sm.treecol[tid] = tree_emb[tid * H_ + h];
    if (tid < QT) { sm.mrow[tid] = -1e30f; sm.lrow[tid] = 0.f; }
    for (int e = tid; e < QT * RV_; e += 256) sm.bucket[0][e] = 0.f;

    const int q0 = (tid >> 4) << 2;       // 0,4,...,60
    const int kl = tid & 15;              // QK key lanes
    const int d0 = (tid & 15) << 2;       // AV dim group
    float oacc[4][4] = {};

    __syncthreads();

    for (int c = 0; c < NCHUNK; c++) {
        const int kb = c * KT;
        const float* ktile = g_k + (size_t)(bh * L_ + kb) * D_;
        const float* vtile = g_v + (size_t)(bh * L_ + kb) * D_;
        for (int e = tid * 4; e < KT * D_; e += 1024) {
            float4 kv = *(const float4*)&ktile[e];
            const int kk = e >> 6, dd = e & 63;
            sm.Ks[kk][dd+0] = kv.x; sm.Ks[kk][dd+1] = kv.y;
            sm.Ks[kk][dd+2] = kv.z; sm.Ks[kk][dd+3] = kv.w;
            *(float4*)&sm.Vs[0][e] = *(const float4*)&vtile[e];
        }
        __syncthreads();

        // ---- QK^T: 4q x 4k per thread ----
        {
            float sacc[4][4] = {};
#pragma unroll 16
            for (int d = 0; d < D_; d++) {
                float a0 = sm.Qs[q0+0][d], a1 = sm.Qs[q0+1][d];
                float a2 = sm.Qs[q0+2][d], a3 = sm.Qs[q0+3][d];
                float b0 = sm.Ks[kl+ 0][d], b1 = sm.Ks[kl+16][d];
                float b2 = sm.Ks[kl+32][d], b3 = sm.Ks[kl+48][d];
                sacc[0][0]+=a0*b0; sacc[0][1]+=a0*b1; sacc[0][2]+=a0*b2; sacc[0][3]+=a0*b3;
                sacc[1][0]+=a1*b0; sacc[1][1]+=a1*b1; sacc[1][2]+=a1*b2; sacc[1][3]+=a1*b3;
                sacc[2][0]+=a2*b0; sacc[2][1]+=a2*b1; sacc[2][2]+=a2*b2; sacc[2][3]+=a2*b3;
                sacc[3][0]+=a3*b0; sacc[3][1]+=a3*b1; sacc[3][2]+=a3*b2; sacc[3][3]+=a3*b3;
            }
#pragma unroll
            for (int i = 0; i < 4; i++)
#pragma unroll
                for (int j = 0; j < 4; j++)
                    sm.S[q0+i][kl + 16*j] = sacc[i][j];
        }
        __syncthreads();

        // ---- bias + mask (coalesced along k) ----
        {
            const int kk2 = tid & 63;
            const int qq0 = tid >> 6;
            const int kg  = kb + kk2;
#pragma unroll
            for (int i = 0; i < 16; i++) {
                const int qq = qq0 + i * 4;
                const int qg = qbase + qq;
                const size_t idx = (size_t)(b * L_ + qg) * L_ + kg;
                const int rm = rel_matrix[idx];
                const float rmk = rel_mask[idx];
                const unsigned char mk = mask[idx];
                int r = kg - qg; r = max(-32, min(32, r)) + 32;
                float sv = sm.S[qq][kk2] + sm.QRs[qq][r] + sm.treecol[rm] * rmk;
                sm.S[qq][kk2] = mk ? -1e18f : sv;
            }
        }
        __syncthreads();

        // ---- online softmax: chunk max ----
        {
            const int qr = tid & 63, sl = tid >> 6;
            float pm = -1e30f;
#pragma unroll
            for (int j = 0; j < 16; j++) pm = fmaxf(pm, sm.S[qr][sl*16 + j]);
            sm.red[qr][sl] = pm;
        }
        __syncthreads();
        if (tid < QT) {
            const float mo = sm.mrow[tid];
            float mn = fmaxf(fmaxf(sm.red[tid][0], sm.red[tid][1]),
                             fmaxf(sm.red[tid][2], sm.red[tid][3]));
            mn = fmaxf(mo, mn);
            sm.mrow[tid]    = mn;
            sm.alpha_s[tid] = fast_exp(mo - mn);
        }
        __syncthreads();

        // ---- rescale running state ----
        for (int e = tid; e < QT * RV_; e += 256) sm.bucket[0][e] *= sm.alpha_s[e / RV_];
        if (tid < QT) sm.lrow[tid] *= sm.alpha_s[tid];
#pragma unroll
        for (int i = 0; i < 4; i++) {
            const float al = sm.alpha_s[q0 + i];
#pragma unroll
            for (int j = 0; j < 4; j++) oacc[i][j] *= al;
        }
        __syncthreads();

        // ---- exp + bucket accumulation ----
        {
            const int qr = tid & 63, sl = tid >> 6;
            const int qg = qbase + qr;
            const float mq = sm.mrow[qr];
            float lsum = 0.f, lo = 0.f, hi = 0.f;
#pragma unroll
            for (int j = 0; j < 16; j++) {
                const int kk2 = sl * 16 + j;
                float p = fast_exp(sm.S[qr][kk2] - mq);
                sm.S[qr][kk2] = p;
                lsum += p;
                const int rd = kb + kk2 - qg;
                if (rd <= -32)      lo += p;
                else if (rd >= 32)  hi += p;
                else                sm.bucket[qr][rd + 32] += p;  // unique (q,r) per thread
            }
            sm.red[qr][sl] = lsum; sm.redlo[qr][sl] = lo; sm.redhi[qr][sl] = hi;
        }
        __syncthreads();
        if (tid < QT) {
            sm.lrow[tid] += sm.red[tid][0] + sm.red[tid][1] + sm.red[tid][2] + sm.red[tid][3];
            sm.bucket[tid][0]     += sm.redlo[tid][0] + sm.redlo[tid][1] + sm.redlo[tid][2] + sm.redlo[tid][3];
            sm.bucket[tid][RV_-1] += sm.redhi[tid][0] + sm.redhi[tid][1] + sm.redhi[tid][2] + sm.redhi[tid][3];
        }
        __syncthreads();

        // ---- P @ V ----
        {
#pragma unroll 8
            for (int kk = 0; kk < KT; kk++) {
                float4 vv = *(const float4*)&sm.Vs[kk][d0];
                float p0 = sm.S[q0+0][kk], p1 = sm.S[q0+1][kk];
                float p2 = sm.S[q0+2][kk], p3 = sm.S[q0+3][kk];
                oacc[0][0]+=p0*vv.x; oacc[0][1]+=p0*vv.y; oacc[0][2]+=p0*vv.z; oacc[0][3]+=p0*vv.w;
                oacc[1][0]+=p1*vv.x; oacc[1][1]+=p1*vv.y; oacc[1][2]+=p1*vv.z; oacc[1][3]+=p1*vv.w;
                oacc[2][0]+=p2*vv.x; oacc[2][1]+=p2*vv.y; oacc[2][2]+=p2*vv.z; oacc[2][3]+=p2*vv.w;
                oacc[3][0]+=p3*vv.x; oacc[3][1]+=p3*vv.y; oacc[3][2]+=p3*vv.z; oacc[3][3]+=p3*vv.w;
            }
        }
        __syncthreads();
    }

    // ---- rel_v context from buckets ----
#pragma unroll 5
    for (int r = 0; r < RV_; r++) {
        float4 rv = *(const float4*)&sm.relv[r][d0];
        float b0 = sm.bucket[q0+0][r], b1 = sm.bucket[q0+1][r];
        float b2 = sm.bucket[q0+2][r], b3 = sm.bucket[q0+3][r];
        oacc[0][0]+=b0*rv.x; oacc[0][1]+=b0*rv.y; oacc[0][2]+=b0*rv.z; oacc[0][3]+=b0*rv.w;
        oacc[1][0]+=b1*rv.x; oacc[1][1]+=b1*rv.y; oacc[1][2]+=b1*rv.z; oacc[1][3]+=b1*rv.w;
        oacc[2][0]+=b2*rv.x; oacc[2][1]+=b2*rv.y; oacc[2][2]+=b2*rv.z; oacc[2][3]+=b2*rv.w;
        oacc[3][0]+=b3*rv.x; oacc[3][1]+=b3*rv.y; oacc[3][2]+=b3*rv.z; oacc[3][3]+=b3*rv.w;
    }

    // ---- normalize + write ctx [b*l, h*64+d] ----
#pragma unroll
    for (int i = 0; i < 4; i++) {
        const float inv = 1.0f / sm.lrow[q0 + i];
        float4 o;
        o.x = oacc[i][0] * inv; o.y = oacc[i][1] * inv;
        o.z = oacc[i][2] * inv; o.w = oacc[i][3] * inv;
        *(float4*)&g_ctx[(size_t)(b * L_ + qbase + q0 + i) * DM_ + h * D_ + d0] = o;
    }
}

// ============================ launch ============================
extern "C" void kernel_launch(void* const* d_in, const int* in_sizes, int n_in,
                              void* d_out, int out_size)
{
    const float* key        = (const float*)d_in[0];
    const float* value      = (const float*)d_in[1];
    const float* query      = (const float*)d_in[2];
    const unsigned char* mask = (const unsigned char*)d_in[3];
    const int*   rel_matrix = (const int*)d_in[4];
    const float* rel_mask   = (const float*)d_in[5];
    const float* Wk = (const float*)d_in[6];
    const float* bk = (const float*)d_in[7];
    const float* Wq = (const float*)d_in[8];
    const float* bq = (const float*)d_in[9];
    const float* Wv = (const float*)d_in[10];
    const float* bv = (const float*)d_in[11];
    const float* Wo = (const float*)d_in[12];
    const float* bo = (const float*)d_in[13];
    const float* rel_emb_k  = (const float*)d_in[14];
    const float* rel_emb_v  = (const float*)d_in[15];
    const float* tree_emb   = (const float*)d_in[16];

    static bool attr_set = false;
    if (!attr_set) {
        cudaFuncSetAttribute(attn_kernel, cudaFuncAttributeMaxDynamicSharedMemorySize,
                             (int)sizeof(AttnSmem));
        attr_set = true;
    }

    dim3 gemm_grid(B_ * L_ / 128, DM_ / 64);             // (64, 8)

    gemm_tc<1><<<gemm_grid, 256>>>(query, Wq, bq, nullptr, 0.125f); // q scaled 1/sqrt(64)
    gemm_tc<2><<<gemm_grid, 256>>>(key,   Wk, bk, nullptr, 1.0f);
    gemm_tc<3><<<gemm_grid, 256>>>(value, Wv, bv, nullptr, 1.0f);

    qrel_kernel<<<(B_ * H_ * L_) / 16, 256>>>(rel_emb_k);

    attn_kernel<<<dim3(L_ / QT, H_, B_), 256, sizeof(AttnSmem)>>>(
        rel_matrix, rel_mask, mask, tree_emb, rel_emb_v);

    gemm_tc<0><<<gemm_grid, 256>>>(nullptr, Wo, bo, (float*)d_out, 1.0f);
}

// round 4
// speedup vs baseline: 1.7429x; 1.5208x over previous
#include <cuda_runtime.h>
#include <math.h>

#define B_   8
#define H_   8
#define L_   1024
#define D_   64
#define DM_  512
#define RV_  65
#define QT   64
#define KT   64
#define NCHUNK (L_/KT)

__device__ float g_q[B_*H_*L_*D_];
__device__ float g_k[B_*H_*L_*D_];
__device__ float g_v[B_*H_*L_*D_];
__device__ float g_qrel[B_*H_*L_*RV_];
__device__ float g_ctx[B_*L_*DM_];

// ---------------- fast exp on FMA pipe ----------------
__device__ __forceinline__ float fast_exp(float x) {
    x = fmaxf(x, -80.0f);
    float t = x * 1.4426950408889634f;
    int   e = __float2int_rn(t);
    float f = t - (float)e;
    float p = 1.3333558146428443e-3f;
    p = fmaf(p, f, 9.6181291976983960e-3f);
    p = fmaf(p, f, 5.5504108664821580e-2f);
    p = fmaf(p, f, 2.4022650695910071e-1f);
    p = fmaf(p, f, 6.9314718055994531e-1f);
    p = fmaf(p, f, 1.0f);
    return __int_as_float(__float_as_int(p) + (e << 23));
}

// ---------------- tf32 helpers ----------------
__device__ __forceinline__ unsigned f2tf(float x) {
    unsigned r;
    asm("cvt.rna.tf32.f32 %0, %1;" : "=r"(r) : "f"(x));
    return r;
}
__device__ __forceinline__ void mma_tf32(float c[4], const unsigned a[4], const unsigned b[2]) {
    asm volatile("mma.sync.aligned.m16n8k8.row.col.f32.tf32.tf32.f32 "
        "{%0,%1,%2,%3}, {%4,%5,%6,%7}, {%8,%9}, {%0,%1,%2,%3};\n"
        : "+f"(c[0]), "+f"(c[1]), "+f"(c[2]), "+f"(c[3])
        : "r"(a[0]), "r"(a[1]), "r"(a[2]), "r"(a[3]), "r"(b[0]), "r"(b[1]));
}

// ============================ tensor-core GEMM (unchanged, verified) ============================
template<int MODE>
__global__ void __launch_bounds__(256) gemm_tc(
    const float* __restrict__ Ain, const float* __restrict__ W,
    const float* __restrict__ bias, float* __restrict__ Cout, float scale)
{
    __shared__ __align__(16) unsigned As[128][36];
    __shared__ __align__(16) unsigned Bs[32][68];
    const int tid  = threadIdx.x;
    const int lane = tid & 31;
    const int wid  = tid >> 5;
    const int bm = blockIdx.x * 128, bn = blockIdx.y * 64;
    const int wm = (wid & 3) << 5;
    const int wn = (wid >> 2) << 5;
    const float* Ap = (MODE == 0) ? g_ctx : Ain;

    const int arow = tid >> 1;
    const int acol = (tid & 1) << 4;
    const int brow = tid >> 3;
    const int bcol = (tid & 7) << 3;

    const float* aptr = Ap + (size_t)(bm + arow) * DM_ + acol;

    float4 ra[4], rb[2];
#pragma unroll
    for (int i = 0; i < 4; i++) ra[i] = *(const float4*)(aptr + i * 4);
#pragma unroll
    for (int i = 0; i < 2; i++)
        rb[i] = *(const float4*)(W + (size_t)brow * DM_ + bn + bcol + i * 4);

    float c[2][4][4] = {};
    const int g = lane >> 2, q = lane & 3;

    for (int kt = 0; kt < DM_; kt += 32) {
#pragma unroll
        for (int i = 0; i < 4; i++) {
            As[arow][acol + i*4 + 0] = f2tf(ra[i].x);
            As[arow][acol + i*4 + 1] = f2tf(ra[i].y);
            As[arow][acol + i*4 + 2] = f2tf(ra[i].z);
            As[arow][acol + i*4 + 3] = f2tf(ra[i].w);
        }
#pragma unroll
        for (int i = 0; i < 2; i++) {
            Bs[brow][bcol + i*4 + 0] = f2tf(rb[i].x);
            Bs[brow][bcol + i*4 + 1] = f2tf(rb[i].y);
            Bs[brow][bcol + i*4 + 2] = f2tf(rb[i].z);
            Bs[brow][bcol + i*4 + 3] = f2tf(rb[i].w);
        }
        __syncthreads();

        if (kt + 32 < DM_) {
#pragma unroll
            for (int i = 0; i < 4; i++) ra[i] = *(const float4*)(aptr + kt + 32 + i * 4);
#pragma unroll
            for (int i = 0; i < 2; i++)
                rb[i] = *(const float4*)(W + (size_t)(kt + 32 + brow) * DM_ + bn + bcol + i * 4);
        }

#pragma unroll
        for (int ks = 0; ks < 32; ks += 8) {
            unsigned a[2][4], bb[4][2];
#pragma unroll
            for (int mi = 0; mi < 2; mi++) {
                const int r = wm + (mi << 4) + g;
                a[mi][0] = As[r    ][ks + q    ];
                a[mi][1] = As[r + 8][ks + q    ];
                a[mi][2] = As[r    ][ks + q + 4];
                a[mi][3] = As[r + 8][ks + q + 4];
            }
#pragma unroll
            for (int ni = 0; ni < 4; ni++) {
                bb[ni][0] = Bs[ks + q    ][wn + (ni << 3) + g];
                bb[ni][1] = Bs[ks + q + 4][wn + (ni << 3) + g];
            }
#pragma unroll
            for (int mi = 0; mi < 2; mi++)
#pragma unroll
                for (int ni = 0; ni < 4; ni++)
                    mma_tf32(c[mi][ni], a[mi], bb[ni]);
        }
        __syncthreads();
    }

#pragma unroll
    for (int mi = 0; mi < 2; mi++) {
#pragma unroll
        for (int ni = 0; ni < 4; ni++) {
            const int n0 = bn + wn + (ni << 3) + (q << 1);
            const float b0 = bias[n0], b1 = bias[n0 + 1];
#pragma unroll
            for (int hh = 0; hh < 2; hh++) {
                const int m = bm + wm + (mi << 4) + g + hh * 8;
                float2 o;
                o.x = (c[mi][ni][hh*2 + 0] + b0) * scale;
                o.y = (c[mi][ni][hh*2 + 1] + b1) * scale;
                if (MODE == 0) {
                    *(float2*)&Cout[(size_t)m * DM_ + n0] = o;
                } else {
                    const int b = m >> 10, l = m & 1023;
                    const int h = n0 >> 6, d = n0 & 63;
                    float* dst = (MODE == 1) ? g_q : (MODE == 2) ? g_k : g_v;
                    *(float2*)&dst[(size_t)((b * H_ + h) * L_ + l) * D_ + d] = o;
                }
            }
        }
    }
}

// ============================ qrel: warp-per-row ============================
__global__ void __launch_bounds__(256) qrel_kernel(const float* __restrict__ rel_emb_k)
{
    __shared__ __align__(16) float qs[8][64];
    __shared__ __align__(16) float embT[64][68];  // [d][r]
    const int tid = threadIdx.x;
    const int row0 = blockIdx.x * 8;

    for (int e = tid; e < RV_ * D_; e += 256) {
        const int r = e >> 6, d = e & 63;
        embT[d][r] = rel_emb_k[e];
    }
    if (tid < 128) {
        const int e = tid * 4;
        *(float4*)&qs[0][e] = *(const float4*)(g_q + (size_t)row0 * D_ + e);
    }
    __syncthreads();

    const int wid = tid >> 5, lane = tid & 31;
    float a0 = 0.f, a1 = 0.f, a2 = 0.f;
#pragma unroll
    for (int d = 0; d < 64; d++) {
        const float qd = qs[wid][d];
        a0 = fmaf(qd, embT[d][lane],      a0);
        a1 = fmaf(qd, embT[d][lane + 32], a1);
        a2 = fmaf(qd, embT[d][64],        a2);
    }
    float* dst = g_qrel + (size_t)(row0 + wid) * RV_;
    dst[lane] = a0;
    dst[lane + 32] = a1;
    if (lane == 0) dst[64] = a2;
}

// ============================ fused attention (tensor-core) ============================
struct __align__(16) AttnSmem {
    unsigned Qtf[QT][68];
    unsigned Ktf[KT][68];
    unsigned Vtf[KT][72];
    unsigned Ptf[QT][68];
    float QRs[QT][RV_];
    float bucket[QT][RV_];
    float relv[RV_][D_];
    float red[QT][2];
    float redlo[QT][2];
    float redhi[QT][2];
    float mrow[QT], lrow[QT], alpha_s[QT];
    float treecol[64];
};

__global__ void __launch_bounds__(256, 1) attn_kernel(
    const int* __restrict__ rel_matrix, const float* __restrict__ rel_mask,
    const unsigned char* __restrict__ mask, const float* __restrict__ tree_emb,
    const float* __restrict__ rel_emb_v)
{
    extern __shared__ __align__(16) char smraw[];
    AttnSmem& sm = *reinterpret_cast<AttnSmem*>(smraw);

    const int tid   = threadIdx.x;
    const int lane  = tid & 31;
    const int wid   = tid >> 5;
    const int g     = lane >> 2, q = lane & 3;
    const int wm    = (wid & 3) << 4;      // 0,16,32,48
    const int wn    = (wid >> 2) << 5;     // 0,32
    const int ncol  = wid >> 2;            // 0/1 reduction column
    const int h     = blockIdx.y;
    const int b     = blockIdx.z;
    const int qbase = blockIdx.x * QT;
    const int bh    = b * H_ + h;
    const int m0 = wm + g, m1 = m0 + 8;

    // ---- stage-in ----
    {
        const float* qtile = g_q + (size_t)(bh * L_ + qbase) * D_;
#pragma unroll
        for (int it = 0; it < 4; it++) {
            const int e = tid * 4 + it * 1024;
            float4 v = *(const float4*)&qtile[e];
            unsigned* d = &sm.Qtf[e >> 6][e & 63];
            d[0] = f2tf(v.x); d[1] = f2tf(v.y); d[2] = f2tf(v.z); d[3] = f2tf(v.w);
        }
        const float* qr = g_qrel + (size_t)(bh * L_ + qbase) * RV_;
        for (int e = tid; e < QT * RV_; e += 256) (&sm.QRs[0][0])[e] = qr[e];
        for (int e = tid * 4; e < RV_ * D_; e += 1024)
            *(float4*)&(&sm.relv[0][0])[e] = *(const float4*)&rel_emb_v[e];
        if (tid < 64) sm.treecol[tid] = tree_emb[tid * H_ + h];
        if (tid < QT) { sm.mrow[tid] = -1e30f; sm.lrow[tid] = 0.f; }
        for (int e = tid; e < QT * RV_; e += 256) (&sm.bucket[0][0])[e] = 0.f;
    }

    float oacc[4][4] = {};
    __syncthreads();

    for (int c = 0; c < NCHUNK; c++) {
        const int kb = c * KT;
        // ---- load + convert K,V ----
        {
            const float* ktile = g_k + (size_t)(bh * L_ + kb) * D_;
            const float* vtile = g_v + (size_t)(bh * L_ + kb) * D_;
#pragma unroll
            for (int it = 0; it < 4; it++) {
                const int e = tid * 4 + it * 1024;
                const int kk = e >> 6, dd = e & 63;
                float4 kv = *(const float4*)&ktile[e];
                float4 vv = *(const float4*)&vtile[e];
                unsigned* kd = &sm.Ktf[kk][dd];
                kd[0] = f2tf(kv.x); kd[1] = f2tf(kv.y); kd[2] = f2tf(kv.z); kd[3] = f2tf(kv.w);
                unsigned* vd = &sm.Vtf[kk][dd];
                vd[0] = f2tf(vv.x); vd[1] = f2tf(vv.y); vd[2] = f2tf(vv.z); vd[3] = f2tf(vv.w);
            }
        }
        __syncthreads();

        // ---- QK^T mma ----
        float cs[4][4] = {};
#pragma unroll
        for (int ks = 0; ks < 64; ks += 8) {
            unsigned a[4];
            a[0] = sm.Qtf[m0][ks + q];
            a[1] = sm.Qtf[m1][ks + q];
            a[2] = sm.Qtf[m0][ks + q + 4];
            a[3] = sm.Qtf[m1][ks + q + 4];
#pragma unroll
            for (int ni = 0; ni < 4; ni++) {
                unsigned bf[2];
                const int np = wn + (ni << 3) + g;
                bf[0] = sm.Ktf[np][ks + q];
                bf[1] = sm.Ktf[np][ks + q + 4];
                mma_tf32(cs[ni], a, bf);
            }
        }

        // ---- bias + mask + partial row max (registers) ----
        float pm0 = -1e30f, pm1 = -1e30f;
#pragma unroll
        for (int ni = 0; ni < 4; ni++) {
            const int nl = wn + (ni << 3) + (q << 1);
            const int kg = kb + nl;
#pragma unroll
            for (int hh = 0; hh < 2; hh++) {
                const int m  = hh ? m1 : m0;
                const int qg = qbase + m;
                const size_t idx = (size_t)(b * L_ + qg) * L_ + kg;
                int2   rm2 = *(const int2*)&rel_matrix[idx];
                float2 rk2 = *(const float2*)&rel_mask[idx];
                unsigned short mk2 = *(const unsigned short*)&mask[idx];
                const int rd = kg - qg;
                const int rA = min(max(rd,     -32), 32) + 32;
                const int rB = min(max(rd + 1, -32), 32) + 32;
                float s0 = cs[ni][hh*2+0] + sm.QRs[m][rA] + sm.treecol[rm2.x] * rk2.x;
                float s1 = cs[ni][hh*2+1] + sm.QRs[m][rB] + sm.treecol[rm2.y] * rk2.y;
                if (mk2 & 0x00ff) s0 = -1e18f;
                if (mk2 & 0xff00) s1 = -1e18f;
                cs[ni][hh*2+0] = s0; cs[ni][hh*2+1] = s1;
                if (hh) pm1 = fmaxf(pm1, fmaxf(s0, s1));
                else    pm0 = fmaxf(pm0, fmaxf(s0, s1));
            }
        }
        pm0 = fmaxf(pm0, __shfl_xor_sync(0xffffffffu, pm0, 1));
        pm0 = fmaxf(pm0, __shfl_xor_sync(0xffffffffu, pm0, 2));
        pm1 = fmaxf(pm1, __shfl_xor_sync(0xffffffffu, pm1, 1));
        pm1 = fmaxf(pm1, __shfl_xor_sync(0xffffffffu, pm1, 2));
        if (q == 0) { sm.red[m0][ncol] = pm0; sm.red[m1][ncol] = pm1; }
        __syncthreads();

        if (tid < QT) {
            const float mo = sm.mrow[tid];
            const float mn = fmaxf(mo, fmaxf(sm.red[tid][0], sm.red[tid][1]));
            sm.mrow[tid] = mn;
            const float al = fast_exp(mo - mn);
            sm.alpha_s[tid] = al;
            sm.lrow[tid] *= al;
        }
        __syncthreads();

        // ---- rescale bucket + oacc ----
        {
            float* bk = &sm.bucket[0][0];
            for (int e = tid; e < QT * RV_; e += 256) bk[e] *= sm.alpha_s[e / RV_];
            const float al0 = sm.alpha_s[m0], al1 = sm.alpha_s[m1];
#pragma unroll
            for (int ni = 0; ni < 4; ni++) {
                oacc[ni][0] *= al0; oacc[ni][1] *= al0;
                oacc[ni][2] *= al1; oacc[ni][3] *= al1;
            }
        }
        __syncthreads();

        // ---- exp + P store + bucket + partial sums ----
        {
            const float mq0 = sm.mrow[m0], mq1 = sm.mrow[m1];
            float ls0=0.f, ls1=0.f, lo0=0.f, lo1=0.f, hi0=0.f, hi1=0.f;
#pragma unroll
            for (int ni = 0; ni < 4; ni++) {
                const int nl = wn + (ni << 3) + (q << 1);
                const int kg = kb + nl;
#pragma unroll
                for (int hh = 0; hh < 2; hh++) {
                    const int m  = hh ? m1 : m0;
                    const float mq = hh ? mq1 : mq0;
                    const int qg = qbase + m;
                    const float p0 = fast_exp(cs[ni][hh*2+0] - mq);
                    const float p1 = fast_exp(cs[ni][hh*2+1] - mq);
                    sm.Ptf[m][nl]   = f2tf(p0);
                    sm.Ptf[m][nl+1] = f2tf(p1);
                    const int rd = kg - qg;
                    float lo = 0.f, hi = 0.f;
                    if (rd <= -32)     lo += p0;
                    else if (rd >= 32) hi += p0;
                    else               sm.bucket[m][rd + 32] += p0;
                    if (rd+1 <= -32)     lo += p1;
                    else if (rd+1 >= 32) hi += p1;
                    else                 sm.bucket[m][rd + 33] += p1;
                    if (hh) { ls1 += p0 + p1; lo1 += lo; hi1 += hi; }
                    else    { ls0 += p0 + p1; lo0 += lo; hi0 += hi; }
                }
            }
#pragma unroll
            for (int s = 1; s <= 2; s <<= 1) {
                ls0 += __shfl_xor_sync(0xffffffffu, ls0, s);
                ls1 += __shfl_xor_sync(0xffffffffu, ls1, s);
                lo0 += __shfl_xor_sync(0xffffffffu, lo0, s);
                lo1 += __shfl_xor_sync(0xffffffffu, lo1, s);
                hi0 += __shfl_xor_sync(0xffffffffu, hi0, s);
                hi1 += __shfl_xor_sync(0xffffffffu, hi1, s);
            }
            if (q == 0) {
                sm.red[m0][ncol]   = ls0; sm.red[m1][ncol]   = ls1;
                sm.redlo[m0][ncol] = lo0; sm.redlo[m1][ncol] = lo1;
                sm.redhi[m0][ncol] = hi0; sm.redhi[m1][ncol] = hi1;
            }
        }
        __syncthreads();

        if (tid < QT) {
            sm.lrow[tid] += sm.red[tid][0] + sm.red[tid][1];
            sm.bucket[tid][0]      += sm.redlo[tid][0] + sm.redlo[tid][1];
            sm.bucket[tid][RV_-1]  += sm.redhi[tid][0] + sm.redhi[tid][1];
        }
        __syncthreads();

        // ---- P @ V mma ----
#pragma unroll
        for (int ks = 0; ks < 64; ks += 8) {
            unsigned a[4];
            a[0] = sm.Ptf[m0][ks + q];
            a[1] = sm.Ptf[m1][ks + q];
            a[2] = sm.Ptf[m0][ks + q + 4];
            a[3] = sm.Ptf[m1][ks + q + 4];
#pragma unroll
            for (int ni = 0; ni < 4; ni++) {
                unsigned bf[2];
                const int np = wn + (ni << 3) + g;
                bf[0] = sm.Vtf[ks + q][np];
                bf[1] = sm.Vtf[ks + q + 4][np];
                mma_tf32(oacc[ni], a, bf);
            }
        }
        __syncthreads();
    }

    // ---- bucket @ rel_emb_v via mma (r=0..63), fp32 tail r=64 ----
#pragma unroll
    for (int it = 0; it < 16; it++) {
        const int e = tid + it * 256;       // 0..4095
        const int r0 = e >> 6, c0 = e & 63;
        sm.Ptf[r0][c0] = f2tf(sm.bucket[r0][c0]);   // [q][r]
        sm.Vtf[r0][c0] = f2tf(sm.relv[r0][c0]);     // [r][d]
    }
    __syncthreads();
#pragma unroll
    for (int ks = 0; ks < 64; ks += 8) {
        unsigned a[4];
        a[0] = sm.Ptf[m0][ks + q];
        a[1] = sm.Ptf[m1][ks + q];
        a[2] = sm.Ptf[m0][ks + q + 4];
        a[3] = sm.Ptf[m1][ks + q + 4];
#pragma unroll
        for (int ni = 0; ni < 4; ni++) {
            unsigned bf[2];
            const int np = wn + (ni << 3) + g;
            bf[0] = sm.Vtf[ks + q][np];
            bf[1] = sm.Vtf[ks + q + 4][np];
            mma_tf32(oacc[ni], a, bf);
        }
    }
    {
        const float bw0 = sm.bucket[m0][64], bw1 = sm.bucket[m1][64];
        const float inv0 = 1.0f / sm.lrow[m0], inv1 = 1.0f / sm.lrow[m1];
#pragma unroll
        for (int ni = 0; ni < 4; ni++) {
            const int nl = wn + (ni << 3) + (q << 1);
            const float rv0 = sm.relv[64][nl], rv1 = sm.relv[64][nl + 1];
            float2 o0, o1;
            o0.x = (oacc[ni][0] + bw0 * rv0) * inv0;
            o0.y = (oacc[ni][1] + bw0 * rv1) * inv0;
            o1.x = (oacc[ni][2] + bw1 * rv0) * inv1;
            o1.y = (oacc[ni][3] + bw1 * rv1) * inv1;
            *(float2*)&g_ctx[(size_t)(b * L_ + qbase + m0) * DM_ + h * D_ + nl] = o0;
            *(float2*)&g_ctx[(size_t)(b * L_ + qbase + m1) * DM_ + h * D_ + nl] = o1;
        }
    }
}

// ============================ launch ============================
extern "C" void kernel_launch(void* const* d_in, const int* in_sizes, int n_in,
                              void* d_out, int out_size)
{
    const float* key        = (const float*)d_in[0];
    const float* value      = (const float*)d_in[1];
    const float* query      = (const float*)d_in[2];
    const unsigned char* mask = (const unsigned char*)d_in[3];
    const int*   rel_matrix = (const int*)d_in[4];
    const float* rel_mask   = (const float*)d_in[5];
    const float* Wk = (const float*)d_in[6];
    const float* bk = (const float*)d_in[7];
    const float* Wq = (const float*)d_in[8];
    const float* bq = (const float*)d_in[9];
    const float* Wv = (const float*)d_in[10];
    const float* bv = (const float*)d_in[11];
    const float* Wo = (const float*)d_in[12];
    const float* bo = (const float*)d_in[13];
    const float* rel_emb_k  = (const float*)d_in[14];
    const float* rel_emb_v  = (const float*)d_in[15];
    const float* tree_emb   = (const float*)d_in[16];

    static bool attr_set = false;
    if (!attr_set) {
        cudaFuncSetAttribute(attn_kernel, cudaFuncAttributeMaxDynamicSharedMemorySize,
                             (int)sizeof(AttnSmem));
        attr_set = true;
    }

    dim3 gemm_grid(B_ * L_ / 128, DM_ / 64);

    gemm_tc<1><<<gemm_grid, 256>>>(query, Wq, bq, nullptr, 0.125f);
    gemm_tc<2><<<gemm_grid, 256>>>(key,   Wk, bk, nullptr, 1.0f);
    gemm_tc<3><<<gemm_grid, 256>>>(value, Wv, bv, nullptr, 1.0f);

    qrel_kernel<<<(B_ * H_ * L_) / 8, 256>>>(rel_emb_k);

    attn_kernel<<<dim3(L_ / QT, H_, B_), 256, sizeof(AttnSmem)>>>(
        rel_matrix, rel_mask, mask, tree_emb, rel_emb_v);

    gemm_tc<0><<<gemm_grid, 256>>>(nullptr, Wo, bo, (float*)d_out, 1.0f);
}

// round 5
// speedup vs baseline: 2.4110x; 1.3833x over previous
#include <cuda_runtime.h>
#include <math.h>

#define B_   8
#define H_   8
#define L_   1024
#define D_   64
#define DM_  512
#define RV_  65
#define QT   64
#define KT   64
#define NCHUNK (L_/KT)

__device__ float g_q[B_*H_*L_*D_];
__device__ float g_k[B_*H_*L_*D_];
__device__ float g_v[B_*H_*L_*D_];
__device__ float g_ctx[B_*L_*DM_];

// ---------------- fast exp on FMA pipe ----------------
__device__ __forceinline__ float fast_exp(float x) {
    x = fmaxf(x, -80.0f);
    float t = x * 1.4426950408889634f;
    int   e = __float2int_rn(t);
    float f = t - (float)e;
    float p = 1.3333558146428443e-3f;
    p = fmaf(p, f, 9.6181291976983960e-3f);
    p = fmaf(p, f, 5.5504108664821580e-2f);
    p = fmaf(p, f, 2.4022650695910071e-1f);
    p = fmaf(p, f, 6.9314718055994531e-1f);
    p = fmaf(p, f, 1.0f);
    return __int_as_float(__float_as_int(p) + (e << 23));
}

// ---------------- tf32 helpers ----------------
__device__ __forceinline__ unsigned f2tf(float x) {
    unsigned r;
    asm("cvt.rna.tf32.f32 %0, %1;" : "=r"(r) : "f"(x));
    return r;
}
__device__ __forceinline__ void mma_tf32(float c[4], const unsigned a[4], const unsigned b[2]) {
    asm volatile("mma.sync.aligned.m16n8k8.row.col.f32.tf32.tf32.f32 "
        "{%0,%1,%2,%3}, {%4,%5,%6,%7}, {%8,%9}, {%0,%1,%2,%3};\n"
        : "+f"(c[0]), "+f"(c[1]), "+f"(c[2]), "+f"(c[3])
        : "r"(a[0]), "r"(a[1]), "r"(a[2]), "r"(a[3]), "r"(b[0]), "r"(b[1]));
}

// ============================ tensor-core GEMM (verified) ============================
template<int MODE>
__global__ void __launch_bounds__(256) gemm_tc(
    const float* __restrict__ Ain, const float* __restrict__ W,
    const float* __restrict__ bias, float* __restrict__ Cout, float scale)
{
    __shared__ __align__(16) unsigned As[128][36];
    __shared__ __align__(16) unsigned Bs[32][68];
    const int tid  = threadIdx.x;
    const int lane = tid & 31;
    const int wid  = tid >> 5;
    const int bm = blockIdx.x * 128, bn = blockIdx.y * 64;
    const int wm = (wid & 3) << 5;
    const int wn = (wid >> 2) << 5;
    const float* Ap = (MODE == 0) ? g_ctx : Ain;

    const int arow = tid >> 1;
    const int acol = (tid & 1) << 4;
    const int brow = tid >> 3;
    const int bcol = (tid & 7) << 3;

    const float* aptr = Ap + (size_t)(bm + arow) * DM_ + acol;

    float4 ra[4], rb[2];
#pragma unroll
    for (int i = 0; i < 4; i++) ra[i] = *(const float4*)(aptr + i * 4);
#pragma unroll
    for (int i = 0; i < 2; i++)
        rb[i] = *(const float4*)(W + (size_t)brow * DM_ + bn + bcol + i * 4);

    float c[2][4][4] = {};
    const int g = lane >> 2, q = lane & 3;

    for (int kt = 0; kt < DM_; kt += 32) {
#pragma unroll
        for (int i = 0; i < 4; i++) {
            As[arow][acol + i*4 + 0] = f2tf(ra[i].x);
            As[arow][acol + i*4 + 1] = f2tf(ra[i].y);
            As[arow][acol + i*4 + 2] = f2tf(ra[i].z);
            As[arow][acol + i*4 + 3] = f2tf(ra[i].w);
        }
#pragma unroll
        for (int i = 0; i < 2; i++) {
            Bs[brow][bcol + i*4 + 0] = f2tf(rb[i].x);
            Bs[brow][bcol + i*4 + 1] = f2tf(rb[i].y);
            Bs[brow][bcol + i*4 + 2] = f2tf(rb[i].z);
            Bs[brow][bcol + i*4 + 3] = f2tf(rb[i].w);
        }
        __syncthreads();

        if (kt + 32 < DM_) {
#pragma unroll
            for (int i = 0; i < 4; i++) ra[i] = *(const float4*)(aptr + kt + 32 + i * 4);
#pragma unroll
            for (int i = 0; i < 2; i++)
                rb[i] = *(const float4*)(W + (size_t)(kt + 32 + brow) * DM_ + bn + bcol + i * 4);
        }

#pragma unroll
        for (int ks = 0; ks < 32; ks += 8) {
            unsigned a[2][4], bb[4][2];
#pragma unroll
            for (int mi = 0; mi < 2; mi++) {
                const int r = wm + (mi << 4) + g;
                a[mi][0] = As[r    ][ks + q    ];
                a[mi][1] = As[r + 8][ks + q    ];
                a[mi][2] = As[r    ][ks + q + 4];
                a[mi][3] = As[r + 8][ks + q + 4];
            }
#pragma unroll
            for (int ni = 0; ni < 4; ni++) {
                bb[ni][0] = Bs[ks + q    ][wn + (ni << 3) + g];
                bb[ni][1] = Bs[ks + q + 4][wn + (ni << 3) + g];
            }
#pragma unroll
            for (int mi = 0; mi < 2; mi++)
#pragma unroll
                for (int ni = 0; ni < 4; ni++)
                    mma_tf32(c[mi][ni], a[mi], bb[ni]);
        }
        __syncthreads();
    }

#pragma unroll
    for (int mi = 0; mi < 2; mi++) {
#pragma unroll
        for (int ni = 0; ni < 4; ni++) {
            const int n0 = bn + wn + (ni << 3) + (q << 1);
            const float b0 = bias[n0], b1 = bias[n0 + 1];
#pragma unroll
            for (int hh = 0; hh < 2; hh++) {
                const int m = bm + wm + (mi << 4) + g + hh * 8;
                float2 o;
                o.x = (c[mi][ni][hh*2 + 0] + b0) * scale;
                o.y = (c[mi][ni][hh*2 + 1] + b1) * scale;
                if (MODE == 0) {
                    *(float2*)&Cout[(size_t)m * DM_ + n0] = o;
                } else {
                    const int b = m >> 10, l = m & 1023;
                    const int h = n0 >> 6, d = n0 & 63;
                    float* dst = (MODE == 1) ? g_q : (MODE == 2) ? g_k : g_v;
                    *(float2*)&dst[(size_t)((b * H_ + h) * L_ + l) * D_ + d] = o;
                }
            }
        }
    }
}

// ============================ fused attention (tensor-core, occ 2) ============================
struct __align__(16) AttnSmem {
    unsigned Qtf[QT][68];
    unsigned Ktf[KT][68];
    unsigned Vtf[KT][72];
    unsigned Ptf[QT][68];
    float QRs[QT][RV_];
    float bucket[QT][RV_];     // interior buckets (cols 1..63 used)
    float red[QT][2];
    float redlo[QT][2];
    float redhi[QT][2];
    float mrow[QT], lrow[QT], alpha_s[QT], pscale[QT], blo[QT], bhi[QT];
    float treecol[64];
};

__global__ void __launch_bounds__(256, 2) attn_kernel(
    const int* __restrict__ rel_matrix, const float* __restrict__ rel_mask,
    const unsigned char* __restrict__ mask, const float* __restrict__ tree_emb,
    const float* __restrict__ rel_emb_k, const float* __restrict__ rel_emb_v)
{
    extern __shared__ __align__(16) char smraw[];
    AttnSmem& sm = *reinterpret_cast<AttnSmem*>(smraw);

    const int tid   = threadIdx.x;
    const int lane  = tid & 31;
    const int wid   = tid >> 5;
    const int g     = lane >> 2, q = lane & 3;
    const int wm    = (wid & 3) << 4;
    const int wn    = (wid >> 2) << 5;
    const int ncol  = wid >> 2;
    const int h     = blockIdx.y;
    const int b     = blockIdx.z;
    const int qbase = blockIdx.x * QT;
    const int bh    = b * H_ + h;
    const int m0 = wm + g, m1 = m0 + 8;

    // ---- stage-in: Q -> Qtf, rel_emb_k(0..63) -> Ktf ----
    {
        const float* qtile = g_q + (size_t)(bh * L_ + qbase) * D_;
#pragma unroll
        for (int it = 0; it < 4; it++) {
            const int e = tid * 4 + it * 1024;
            float4 v = *(const float4*)&qtile[e];
            unsigned* d = &sm.Qtf[e >> 6][e & 63];
            d[0] = f2tf(v.x); d[1] = f2tf(v.y); d[2] = f2tf(v.z); d[3] = f2tf(v.w);
            float4 r = *(const float4*)&rel_emb_k[e];
            unsigned* kd = &sm.Ktf[e >> 6][e & 63];
            kd[0] = f2tf(r.x); kd[1] = f2tf(r.y); kd[2] = f2tf(r.z); kd[3] = f2tf(r.w);
        }
        if (tid < 64) sm.treecol[tid] = tree_emb[tid * H_ + h];
        if (tid < QT) {
            sm.mrow[tid] = -1e30f; sm.lrow[tid] = 0.f;
            sm.blo[tid] = 0.f; sm.bhi[tid] = 0.f; sm.pscale[tid] = 1.f;
        }
        for (int e = tid; e < QT * RV_; e += 256) (&sm.bucket[0][0])[e] = 0.f;
    }
    __syncthreads();

    // ---- QRs = Q @ rel_emb_k^T via mma (r=0..63) + fp32 tail r=64 ----
    {
        float cq[4][4] = {};
#pragma unroll
        for (int ks = 0; ks < 64; ks += 8) {
            unsigned a[4];
            a[0] = sm.Qtf[m0][ks + q];
            a[1] = sm.Qtf[m1][ks + q];
            a[2] = sm.Qtf[m0][ks + q + 4];
            a[3] = sm.Qtf[m1][ks + q + 4];
#pragma unroll
            for (int ni = 0; ni < 4; ni++) {
                unsigned bf[2];
                const int np = wn + (ni << 3) + g;
                bf[0] = sm.Ktf[np][ks + q];
                bf[1] = sm.Ktf[np][ks + q + 4];
                mma_tf32(cq[ni], a, bf);
            }
        }
#pragma unroll
        for (int ni = 0; ni < 4; ni++) {
            const int nl = wn + (ni << 3) + (q << 1);
            sm.QRs[m0][nl] = cq[ni][0]; sm.QRs[m0][nl+1] = cq[ni][1];
            sm.QRs[m1][nl] = cq[ni][2]; sm.QRs[m1][nl+1] = cq[ni][3];
        }
        if (tid < 64) {
            float s = 0.f;
#pragma unroll
            for (int d = 0; d < 64; d++)
                s = fmaf(__uint_as_float(sm.Qtf[tid][d]), rel_emb_k[64 * 64 + d], s);
            sm.QRs[tid][64] = s;
        }
    }
    __syncthreads();

    float oacc[4][4] = {};

    for (int c = 0; c < NCHUNK; c++) {
        const int kb   = c * KT;
        const int diff = kb - qbase;
        const bool near = (diff >= -64) && (diff <= 64);

        // ---- load + convert K,V ----
        {
            const float* ktile = g_k + (size_t)(bh * L_ + kb) * D_;
            const float* vtile = g_v + (size_t)(bh * L_ + kb) * D_;
#pragma unroll
            for (int it = 0; it < 4; it++) {
                const int e = tid * 4 + it * 1024;
                const int kk = e >> 6, dd = e & 63;
                float4 kv = *(const float4*)&ktile[e];
                float4 vv = *(const float4*)&vtile[e];
                unsigned* kd = &sm.Ktf[kk][dd];
                kd[0] = f2tf(kv.x); kd[1] = f2tf(kv.y); kd[2] = f2tf(kv.z); kd[3] = f2tf(kv.w);
                unsigned* vd = &sm.Vtf[kk][dd];
                vd[0] = f2tf(vv.x); vd[1] = f2tf(vv.y); vd[2] = f2tf(vv.z); vd[3] = f2tf(vv.w);
            }
        }
        __syncthreads();

        // ---- QK^T mma ----
        float cs[4][4] = {};
#pragma unroll
        for (int ks = 0; ks < 64; ks += 8) {
            unsigned a[4];
            a[0] = sm.Qtf[m0][ks + q];
            a[1] = sm.Qtf[m1][ks + q];
            a[2] = sm.Qtf[m0][ks + q + 4];
            a[3] = sm.Qtf[m1][ks + q + 4];
#pragma unroll
            for (int ni = 0; ni < 4; ni++) {
                unsigned bf[2];
                const int np = wn + (ni << 3) + g;
                bf[0] = sm.Ktf[np][ks + q];
                bf[1] = sm.Ktf[np][ks + q + 4];
                mma_tf32(cs[ni], a, bf);
            }
        }

        // ---- bias + mask + partial row max ----
        float pm0 = -1e30f, pm1 = -1e30f;
#pragma unroll
        for (int ni = 0; ni < 4; ni++) {
            const int nl = wn + (ni << 3) + (q << 1);
            const int kg = kb + nl;
#pragma unroll
            for (int hh = 0; hh < 2; hh++) {
                const int m  = hh ? m1 : m0;
                const int qg = qbase + m;
                const size_t idx = (size_t)(b * L_ + qg) * L_ + kg;
                int2   rm2 = *(const int2*)&rel_matrix[idx];
                float2 rk2 = *(const float2*)&rel_mask[idx];
                unsigned short mk2 = *(const unsigned short*)&mask[idx];
                const int rd = kg - qg;
                const int rA = min(max(rd,     -32), 32) + 32;
                const int rB = min(max(rd + 1, -32), 32) + 32;
                float s0 = cs[ni][hh*2+0] + sm.QRs[m][rA] + sm.treecol[rm2.x] * rk2.x;
                float s1 = cs[ni][hh*2+1] + sm.QRs[m][rB] + sm.treecol[rm2.y] * rk2.y;
                if (mk2 & 0x00ff) s0 = -1e18f;
                if (mk2 & 0xff00) s1 = -1e18f;
                cs[ni][hh*2+0] = s0; cs[ni][hh*2+1] = s1;
                if (hh) pm1 = fmaxf(pm1, fmaxf(s0, s1));
                else    pm0 = fmaxf(pm0, fmaxf(s0, s1));
            }
        }
        pm0 = fmaxf(pm0, __shfl_xor_sync(0xffffffffu, pm0, 1));
        pm0 = fmaxf(pm0, __shfl_xor_sync(0xffffffffu, pm0, 2));
        pm1 = fmaxf(pm1, __shfl_xor_sync(0xffffffffu, pm1, 1));
        pm1 = fmaxf(pm1, __shfl_xor_sync(0xffffffffu, pm1, 2));
        if (q == 0) { sm.red[m0][ncol] = pm0; sm.red[m1][ncol] = pm1; }
        __syncthreads();

        if (tid < QT) {
            const float mo = sm.mrow[tid];
            const float mn = fmaxf(mo, fmaxf(sm.red[tid][0], sm.red[tid][1]));
            sm.mrow[tid] = mn;
            const float al = fast_exp(mo - mn);
            sm.alpha_s[tid] = al;
            sm.lrow[tid]   *= al;
            sm.blo[tid]    *= al;
            sm.bhi[tid]    *= al;
            sm.pscale[tid] *= al;
        }
        __syncthreads();

        // oacc rescale (registers)
        {
            const float al0 = sm.alpha_s[m0], al1 = sm.alpha_s[m1];
#pragma unroll
            for (int ni = 0; ni < 4; ni++) {
                oacc[ni][0] *= al0; oacc[ni][1] *= al0;
                oacc[ni][2] *= al1; oacc[ni][3] *= al1;
            }
        }

        if (near) {
            // flush pending scale into interior buckets before scatter
            float* bk = &sm.bucket[0][0];
            for (int e = tid; e < QT * RV_; e += 256) bk[e] *= sm.pscale[e / RV_];
            __syncthreads();
        }

        // ---- exp + P store (+ bucket scatter on near chunks) ----
        {
            const float mq0 = sm.mrow[m0], mq1 = sm.mrow[m1];
            float ls0 = 0.f, ls1 = 0.f, lo0 = 0.f, lo1 = 0.f, hi0 = 0.f, hi1 = 0.f;
#pragma unroll
            for (int ni = 0; ni < 4; ni++) {
                const int nl = wn + (ni << 3) + (q << 1);
                const int kg = kb + nl;
#pragma unroll
                for (int hh = 0; hh < 2; hh++) {
                    const int m  = hh ? m1 : m0;
                    const float mq = hh ? mq1 : mq0;
                    const float p0 = fast_exp(cs[ni][hh*2+0] - mq);
                    const float p1 = fast_exp(cs[ni][hh*2+1] - mq);
                    sm.Ptf[m][nl]   = f2tf(p0);
                    sm.Ptf[m][nl+1] = f2tf(p1);
                    if (near) {
                        const int qg = qbase + m;
                        const int rd = kg - qg;
                        float lo = 0.f, hi = 0.f;
                        if (rd <= -32)     lo += p0;
                        else if (rd >= 32) hi += p0;
                        else               sm.bucket[m][rd + 32] += p0;
                        if (rd + 1 <= -32)     lo += p1;
                        else if (rd + 1 >= 32) hi += p1;
                        else                   sm.bucket[m][rd + 33] += p1;
                        if (hh) { lo1 += lo; hi1 += hi; }
                        else    { lo0 += lo; hi0 += hi; }
                    }
                    if (hh) ls1 += p0 + p1;
                    else    ls0 += p0 + p1;
                }
            }
#pragma unroll
            for (int s = 1; s <= 2; s <<= 1) {
                ls0 += __shfl_xor_sync(0xffffffffu, ls0, s);
                ls1 += __shfl_xor_sync(0xffffffffu, ls1, s);
                if (near) {
                    lo0 += __shfl_xor_sync(0xffffffffu, lo0, s);
                    lo1 += __shfl_xor_sync(0xffffffffu, lo1, s);
                    hi0 += __shfl_xor_sync(0xffffffffu, hi0, s);
                    hi1 += __shfl_xor_sync(0xffffffffu, hi1, s);
                }
            }
            if (q == 0) {
                sm.red[m0][ncol] = ls0; sm.red[m1][ncol] = ls1;
                if (near) {
                    sm.redlo[m0][ncol] = lo0; sm.redlo[m1][ncol] = lo1;
                    sm.redhi[m0][ncol] = hi0; sm.redhi[m1][ncol] = hi1;
                }
            }
        }
        __syncthreads();

        if (tid < QT) {
            const float s = sm.red[tid][0] + sm.red[tid][1];
            sm.lrow[tid] += s;
            if (near) {
                sm.blo[tid] += sm.redlo[tid][0] + sm.redlo[tid][1];
                sm.bhi[tid] += sm.redhi[tid][0] + sm.redhi[tid][1];
                sm.pscale[tid] = 1.f;       // flush consumed the pending scale
            } else if (diff < 0) {
                sm.blo[tid] += s;
            } else {
                sm.bhi[tid] += s;
            }
        }
        __syncthreads();

        // ---- P @ V mma ----
#pragma unroll
        for (int ks = 0; ks < 64; ks += 8) {
            unsigned a[4];
            a[0] = sm.Ptf[m0][ks + q];
            a[1] = sm.Ptf[m1][ks + q];
            a[2] = sm.Ptf[m0][ks + q + 4];
            a[3] = sm.Ptf[m1][ks + q + 4];
#pragma unroll
            for (int ni = 0; ni < 4; ni++) {
                unsigned bf[2];
                const int np = wn + (ni << 3) + g;
                bf[0] = sm.Vtf[ks + q][np];
                bf[1] = sm.Vtf[ks + q + 4][np];
                mma_tf32(oacc[ni], a, bf);
            }
        }
        __syncthreads();
    }

    // ---- epilogue: bucket @ rel_emb_v (r=0..63 via mma, r=64 fp32 tail) ----
#pragma unroll
    for (int it = 0; it < 16; it++) {
        const int e = tid + it * 256;
        const int r0 = e >> 6, c0 = e & 63;
        const float bval = (c0 == 0) ? sm.blo[r0] : sm.bucket[r0][c0] * sm.pscale[r0];
        sm.Ptf[r0][c0] = f2tf(bval);                       // [q][r]
        sm.Vtf[r0][c0] = f2tf(rel_emb_v[r0 * 64 + c0]);    // [r][d]
    }
    __syncthreads();
#pragma unroll
    for (int ks = 0; ks < 64; ks += 8) {
        unsigned a[4];
        a[0] = sm.Ptf[m0][ks + q];
        a[1] = sm.Ptf[m1][ks + q];
        a[2] = sm.Ptf[m0][ks + q + 4];
        a[3] = sm.Ptf[m1][ks + q + 4];
#pragma unroll
        for (int ni = 0; ni < 4; ni++) {
            unsigned bf[2];
            const int np = wn + (ni << 3) + g;
            bf[0] = sm.Vtf[ks + q][np];
            bf[1] = sm.Vtf[ks + q + 4][np];
            mma_tf32(oacc[ni], a, bf);
        }
    }
    {
        const float bw0 = sm.bhi[m0], bw1 = sm.bhi[m1];
        const float inv0 = 1.0f / sm.lrow[m0], inv1 = 1.0f / sm.lrow[m1];
#pragma unroll
        for (int ni = 0; ni < 4; ni++) {
            const int nl = wn + (ni << 3) + (q << 1);
            const float rv0 = rel_emb_v[64 * 64 + nl], rv1 = rel_emb_v[64 * 64 + nl + 1];
            float2 o0, o1;
            o0.x = (oacc[ni][0] + bw0 * rv0) * inv0;
            o0.y = (oacc[ni][1] + bw0 * rv1) * inv0;
            o1.x = (oacc[ni][2] + bw1 * rv0) * inv1;
            o1.y = (oacc[ni][3] + bw1 * rv1) * inv1;
            *(float2*)&g_ctx[(size_t)(b * L_ + qbase + m0) * DM_ + h * D_ + nl] = o0;
            *(float2*)&g_ctx[(size_t)(b * L_ + qbase + m1) * DM_ + h * D_ + nl] = o1;
        }
    }
}

// ============================ launch ============================
extern "C" void kernel_launch(void* const* d_in, const int* in_sizes, int n_in,
                              void* d_out, int out_size)
{
    const float* key        = (const float*)d_in[0];
    const float* value      = (const float*)d_in[1];
    const float* query      = (const float*)d_in[2];
    const unsigned char* mask = (const unsigned char*)d_in[3];
    const int*   rel_matrix = (const int*)d_in[4];
    const float* rel_mask   = (const float*)d_in[5];
    const float* Wk = (const float*)d_in[6];
    const float* bk = (const float*)d_in[7];
    const float* Wq = (const float*)d_in[8];
    const float* bq = (const float*)d_in[9];
    const float* Wv = (const float*)d_in[10];
    const float* bv = (const float*)d_in[11];
    const float* Wo = (const float*)d_in[12];
    const float* bo = (const float*)d_in[13];
    const float* rel_emb_k  = (const float*)d_in[14];
    const float* rel_emb_v  = (const float*)d_in[15];
    const float* tree_emb   = (const float*)d_in[16];

    static bool attr_set = false;
    if (!attr_set) {
        cudaFuncSetAttribute(attn_kernel, cudaFuncAttributeMaxDynamicSharedMemorySize,
                             (int)sizeof(AttnSmem));
        attr_set = true;
    }

    dim3 gemm_grid(B_ * L_ / 128, DM_ / 64);

    gemm_tc<1><<<gemm_grid, 256>>>(query, Wq, bq, nullptr, 0.125f);
    gemm_tc<2><<<gemm_grid, 256>>>(key,   Wk, bk, nullptr, 1.0f);
    gemm_tc<3><<<gemm_grid, 256>>>(value, Wv, bv, nullptr, 1.0f);

    attn_kernel<<<dim3(L_ / QT, H_, B_), 256, sizeof(AttnSmem)>>>(
        rel_matrix, rel_mask, mask, tree_emb, rel_emb_k, rel_emb_v);

    gemm_tc<0><<<gemm_grid, 256>>>(nullptr, Wo, bo, (float*)d_out, 1.0f);
}

// round 6
// speedup vs baseline: 2.6379x; 1.0941x over previous
#include <cuda_runtime.h>
#include <math.h>

#define B_   8
#define H_   8
#define L_   1024
#define D_   64
#define DM_  512
#define RV_  65
#define QT   64
#define KT   64
#define NCHUNK (L_/KT)

__device__ float g_q[B_*H_*L_*D_];
__device__ float g_k[B_*H_*L_*D_];
__device__ float g_v[B_*H_*L_*D_];
__device__ float g_ctx[B_*L_*DM_];

// ---------------- fast exp on FMA pipe ----------------
__device__ __forceinline__ float fast_exp(float x) {
    x = fmaxf(x, -80.0f);
    float t = x * 1.4426950408889634f;
    int   e = __float2int_rn(t);
    float f = t - (float)e;
    float p = 1.3333558146428443e-3f;
    p = fmaf(p, f, 9.6181291976983960e-3f);
    p = fmaf(p, f, 5.5504108664821580e-2f);
    p = fmaf(p, f, 2.4022650695910071e-1f);
    p = fmaf(p, f, 6.9314718055994531e-1f);
    p = fmaf(p, f, 1.0f);
    return __int_as_float(__float_as_int(p) + (e << 23));
}

// ---------------- tf32 helpers ----------------
__device__ __forceinline__ unsigned f2tf(float x) {
    unsigned r;
    asm("cvt.rna.tf32.f32 %0, %1;" : "=r"(r) : "f"(x));
    return r;
}
__device__ __forceinline__ void mma_tf32(float c[4], const unsigned a[4], const unsigned b[2]) {
    asm volatile("mma.sync.aligned.m16n8k8.row.col.f32.tf32.tf32.f32 "
        "{%0,%1,%2,%3}, {%4,%5,%6,%7}, {%8,%9}, {%0,%1,%2,%3};\n"
        : "+f"(c[0]), "+f"(c[1]), "+f"(c[2]), "+f"(c[3])
        : "r"(a[0]), "r"(a[1]), "r"(a[2]), "r"(a[3]), "r"(b[0]), "r"(b[1]));
}

// ============================ GEMM core (shared by QKV + out-proj) ============================
template<int MODE>   // 0: out-proj -> Cout, 1: -> g_q/g_k/g_v by zsel
__device__ __forceinline__ void gemm_body(
    const float* __restrict__ Ap, const float* __restrict__ W,
    const float* __restrict__ bias, float* __restrict__ Cout,
    float scale, int zsel)
{
    __shared__ __align__(16) unsigned As[128][36];
    __shared__ __align__(16) unsigned Bs[32][68];
    const int tid  = threadIdx.x;
    const int lane = tid & 31;
    const int wid  = tid >> 5;
    const int bm = blockIdx.x * 128, bn = blockIdx.y * 64;
    const int wm = (wid & 3) << 5;
    const int wn = (wid >> 2) << 5;

    const int arow = tid >> 1;
    const int acol = (tid & 1) << 4;
    const int brow = tid >> 3;
    const int bcol = (tid & 7) << 3;

    const float* aptr = Ap + (size_t)(bm + arow) * DM_ + acol;

    float4 ra[4], rb[2];
#pragma unroll
    for (int i = 0; i < 4; i++) ra[i] = *(const float4*)(aptr + i * 4);
#pragma unroll
    for (int i = 0; i < 2; i++)
        rb[i] = *(const float4*)(W + (size_t)brow * DM_ + bn + bcol + i * 4);

    float c[2][4][4] = {};
    const int g = lane >> 2, q = lane & 3;

    for (int kt = 0; kt < DM_; kt += 32) {
#pragma unroll
        for (int i = 0; i < 4; i++) {
            As[arow][acol + i*4 + 0] = f2tf(ra[i].x);
            As[arow][acol + i*4 + 1] = f2tf(ra[i].y);
            As[arow][acol + i*4 + 2] = f2tf(ra[i].z);
            As[arow][acol + i*4 + 3] = f2tf(ra[i].w);
        }
#pragma unroll
        for (int i = 0; i < 2; i++) {
            Bs[brow][bcol + i*4 + 0] = f2tf(rb[i].x);
            Bs[brow][bcol + i*4 + 1] = f2tf(rb[i].y);
            Bs[brow][bcol + i*4 + 2] = f2tf(rb[i].z);
            Bs[brow][bcol + i*4 + 3] = f2tf(rb[i].w);
        }
        __syncthreads();

        if (kt + 32 < DM_) {
#pragma unroll
            for (int i = 0; i < 4; i++) ra[i] = *(const float4*)(aptr + kt + 32 + i * 4);
#pragma unroll
            for (int i = 0; i < 2; i++)
                rb[i] = *(const float4*)(W + (size_t)(kt + 32 + brow) * DM_ + bn + bcol + i * 4);
        }

#pragma unroll
        for (int ks = 0; ks < 32; ks += 8) {
            unsigned a[2][4], bb[4][2];
#pragma unroll
            for (int mi = 0; mi < 2; mi++) {
                const int r = wm + (mi << 4) + g;
                a[mi][0] = As[r    ][ks + q    ];
                a[mi][1] = As[r + 8][ks + q    ];
                a[mi][2] = As[r    ][ks + q + 4];
                a[mi][3] = As[r + 8][ks + q + 4];
            }
#pragma unroll
            for (int ni = 0; ni < 4; ni++) {
                bb[ni][0] = Bs[ks + q    ][wn + (ni << 3) + g];
                bb[ni][1] = Bs[ks + q + 4][wn + (ni << 3) + g];
            }
#pragma unroll
            for (int mi = 0; mi < 2; mi++)
#pragma unroll
                for (int ni = 0; ni < 4; ni++)
                    mma_tf32(c[mi][ni], a[mi], bb[ni]);
        }
        __syncthreads();
    }

#pragma unroll
    for (int mi = 0; mi < 2; mi++) {
#pragma unroll
        for (int ni = 0; ni < 4; ni++) {
            const int n0 = bn + wn + (ni << 3) + (q << 1);
            const float b0 = bias[n0], b1 = bias[n0 + 1];
#pragma unroll
            for (int hh = 0; hh < 2; hh++) {
                const int m = bm + wm + (mi << 4) + g + hh * 8;
                float2 o;
                o.x = (c[mi][ni][hh*2 + 0] + b0) * scale;
                o.y = (c[mi][ni][hh*2 + 1] + b1) * scale;
                if (MODE == 0) {
                    *(float2*)&Cout[(size_t)m * DM_ + n0] = o;
                } else {
                    const int b = m >> 10, l = m & 1023;
                    const int h = n0 >> 6, d = n0 & 63;
                    float* dst = (zsel == 0) ? g_q : (zsel == 1) ? g_k : g_v;
                    *(float2*)&dst[(size_t)((b * H_ + h) * L_ + l) * D_ + d] = o;
                }
            }
        }
    }
}

__global__ void __launch_bounds__(256) gemm_qkv(
    const float* __restrict__ query, const float* __restrict__ key, const float* __restrict__ value,
    const float* __restrict__ Wq, const float* __restrict__ Wk, const float* __restrict__ Wv,
    const float* __restrict__ bq, const float* __restrict__ bk, const float* __restrict__ bv)
{
    const int z = blockIdx.z;
    const float* A = (z == 0) ? query : (z == 1) ? key : value;
    const float* W = (z == 0) ? Wq : (z == 1) ? Wk : Wv;
    const float* bias = (z == 0) ? bq : (z == 1) ? bk : bv;
    const float scale = (z == 0) ? 0.125f : 1.0f;
    gemm_body<1>(A, W, bias, nullptr, scale, z);
}

__global__ void __launch_bounds__(256) gemm_out(
    const float* __restrict__ Wo, const float* __restrict__ bo, float* __restrict__ Cout)
{
    gemm_body<0>(g_ctx, Wo, bo, Cout, 1.0f, 0);
}

// ============================ fused attention (fixed-shift softmax) ============================
struct __align__(16) AttnSmem {
    unsigned Qtf[QT][68];
    unsigned Ktf[KT][68];
    unsigned Vtf[KT][72];
    unsigned Ptf[QT][68];
    float QRs[QT][RV_];
    float bucket[QT][RV_];      // interior cols 1..63 scattered; 0/64 set in epilogue
    float racc[QT][2];          // running row sums (per-warp owned)
    float rlo[QT][2];
    float rhi[QT][2];
    float lrowf[QT];
    float treecol[64];
};

__global__ void __launch_bounds__(256, 2) attn_kernel(
    const int* __restrict__ rel_matrix, const float* __restrict__ rel_mask,
    const unsigned char* __restrict__ mask, const float* __restrict__ tree_emb,
    const float* __restrict__ rel_emb_k, const float* __restrict__ rel_emb_v)
{
    extern __shared__ __align__(16) char smraw[];
    AttnSmem& sm = *reinterpret_cast<AttnSmem*>(smraw);

    const int tid   = threadIdx.x;
    const int lane  = tid & 31;
    const int wid   = tid >> 5;
    const int g     = lane >> 2, q = lane & 3;
    const int wm    = (wid & 3) << 4;
    const int wn    = (wid >> 2) << 5;
    const int ncol  = wid >> 2;
    const int h     = blockIdx.y;
    const int b     = blockIdx.z;
    const int qbase = blockIdx.x * QT;
    const int bh    = b * H_ + h;
    const int m0 = wm + g, m1 = m0 + 8;

    // ---- stage-in: Q -> Qtf, rel_emb_k(0..63) -> Ktf ----
    {
        const float* qtile = g_q + (size_t)(bh * L_ + qbase) * D_;
#pragma unroll
        for (int it = 0; it < 4; it++) {
            const int e = tid * 4 + it * 1024;
            float4 v = *(const float4*)&qtile[e];
            unsigned* d = &sm.Qtf[e >> 6][e & 63];
            d[0] = f2tf(v.x); d[1] = f2tf(v.y); d[2] = f2tf(v.z); d[3] = f2tf(v.w);
            float4 r = *(const float4*)&rel_emb_k[e];
            unsigned* kd = &sm.Ktf[e >> 6][e & 63];
            kd[0] = f2tf(r.x); kd[1] = f2tf(r.y); kd[2] = f2tf(r.z); kd[3] = f2tf(r.w);
        }
        if (tid < 64) sm.treecol[tid] = tree_emb[tid * H_ + h];
        if (tid < QT) {
            sm.racc[tid][0] = 0.f; sm.racc[tid][1] = 0.f;
            sm.rlo[tid][0]  = 0.f; sm.rlo[tid][1]  = 0.f;
            sm.rhi[tid][0]  = 0.f; sm.rhi[tid][1]  = 0.f;
        }
        for (int e = tid; e < QT * RV_; e += 256) (&sm.bucket[0][0])[e] = 0.f;
    }
    __syncthreads();

    // ---- QRs = Q @ rel_emb_k^T via mma (r=0..63) + fp32 tail r=64 ----
    {
        float cq[4][4] = {};
#pragma unroll
        for (int ks = 0; ks < 64; ks += 8) {
            unsigned a[4];
            a[0] = sm.Qtf[m0][ks + q];
            a[1] = sm.Qtf[m1][ks + q];
            a[2] = sm.Qtf[m0][ks + q + 4];
            a[3] = sm.Qtf[m1][ks + q + 4];
#pragma unroll
            for (int ni = 0; ni < 4; ni++) {
                unsigned bf[2];
                const int np = wn + (ni << 3) + g;
                bf[0] = sm.Ktf[np][ks + q];
                bf[1] = sm.Ktf[np][ks + q + 4];
                mma_tf32(cq[ni], a, bf);
            }
        }
#pragma unroll
        for (int ni = 0; ni < 4; ni++) {
            const int nl = wn + (ni << 3) + (q << 1);
            sm.QRs[m0][nl] = cq[ni][0]; sm.QRs[m0][nl+1] = cq[ni][1];
            sm.QRs[m1][nl] = cq[ni][2]; sm.QRs[m1][nl+1] = cq[ni][3];
        }
        if (tid < 64) {
            float s = 0.f;
#pragma unroll
            for (int d = 0; d < 64; d++)
                s = fmaf(__uint_as_float(sm.Qtf[tid][d]), rel_emb_k[64 * 64 + d], s);
            sm.QRs[tid][64] = s;
        }
    }
    __syncthreads();

    float oacc[4][4] = {};

    for (int c = 0; c < NCHUNK; c++) {
        const int kb   = c * KT;
        const int diff = kb - qbase;
        const bool near = (diff >= -64) && (diff <= 64);

        // ---- load + convert K,V ----
        {
            const float* ktile = g_k + (size_t)(bh * L_ + kb) * D_;
            const float* vtile = g_v + (size_t)(bh * L_ + kb) * D_;
#pragma unroll
            for (int it = 0; it < 4; it++) {
                const int e = tid * 4 + it * 1024;
                const int kk = e >> 6, dd = e & 63;
                float4 kv = *(const float4*)&ktile[e];
                float4 vv = *(const float4*)&vtile[e];
                unsigned* kd = &sm.Ktf[kk][dd];
                kd[0] = f2tf(kv.x); kd[1] = f2tf(kv.y); kd[2] = f2tf(kv.z); kd[3] = f2tf(kv.w);
                unsigned* vd = &sm.Vtf[kk][dd];
                vd[0] = f2tf(vv.x); vd[1] = f2tf(vv.y); vd[2] = f2tf(vv.z); vd[3] = f2tf(vv.w);
            }
        }
        __syncthreads();

        // ---- QK^T mma ----
        float cs[4][4] = {};
#pragma unroll
        for (int ks = 0; ks < 64; ks += 8) {
            unsigned a[4];
            a[0] = sm.Qtf[m0][ks + q];
            a[1] = sm.Qtf[m1][ks + q];
            a[2] = sm.Qtf[m0][ks + q + 4];
            a[3] = sm.Qtf[m1][ks + q + 4];
#pragma unroll
            for (int ni = 0; ni < 4; ni++) {
                unsigned bf[2];
                const int np = wn + (ni << 3) + g;
                bf[0] = sm.Ktf[np][ks + q];
                bf[1] = sm.Ktf[np][ks + q + 4];
                mma_tf32(cs[ni], a, bf);
            }
        }

        // ---- bias + fixed-shift exp + P store + bucket + running sums ----
        {
            float ls0 = 0.f, ls1 = 0.f, lo0 = 0.f, lo1 = 0.f, hi0 = 0.f, hi1 = 0.f;
#pragma unroll
            for (int ni = 0; ni < 4; ni++) {
                const int nl = wn + (ni << 3) + (q << 1);
                const int kg = kb + nl;
#pragma unroll
                for (int hh = 0; hh < 2; hh++) {
                    const int m  = hh ? m1 : m0;
                    const int qg = qbase + m;
                    const size_t idx = (size_t)(b * L_ + qg) * L_ + kg;
                    int2   rm2 = *(const int2*)&rel_matrix[idx];
                    float2 rk2 = *(const float2*)&rel_mask[idx];
                    unsigned short mk2 = *(const unsigned short*)&mask[idx];
                    const int rd = kg - qg;
                    const int rA = min(max(rd,     -32), 32) + 32;
                    const int rB = min(max(rd + 1, -32), 32) + 32;
                    float s0 = cs[ni][hh*2+0] + sm.QRs[m][rA] + sm.treecol[rm2.x] * rk2.x;
                    float s1 = cs[ni][hh*2+1] + sm.QRs[m][rB] + sm.treecol[rm2.y] * rk2.y;
                    if (mk2 & 0x00ff) s0 = -1e18f;
                    if (mk2 & 0xff00) s1 = -1e18f;
                    const float p0 = fast_exp(s0 - 20.0f);
                    const float p1 = fast_exp(s1 - 20.0f);
                    sm.Ptf[m][nl]   = f2tf(p0);
                    sm.Ptf[m][nl+1] = f2tf(p1);
                    if (near) {
                        float lo = 0.f, hi = 0.f;
                        if (rd <= -32)     lo += p0;
                        else if (rd >= 32) hi += p0;
                        else               sm.bucket[m][rd + 32] += p0;
                        if (rd + 1 <= -32)     lo += p1;
                        else if (rd + 1 >= 32) hi += p1;
                        else                   sm.bucket[m][rd + 33] += p1;
                        if (hh) { lo1 += lo; hi1 += hi; }
                        else    { lo0 += lo; hi0 += hi; }
                    }
                    if (hh) ls1 += p0 + p1;
                    else    ls0 += p0 + p1;
                }
            }
#pragma unroll
            for (int s = 1; s <= 2; s <<= 1) {
                ls0 += __shfl_xor_sync(0xffffffffu, ls0, s);
                ls1 += __shfl_xor_sync(0xffffffffu, ls1, s);
                if (near) {
                    lo0 += __shfl_xor_sync(0xffffffffu, lo0, s);
                    lo1 += __shfl_xor_sync(0xffffffffu, lo1, s);
                    hi0 += __shfl_xor_sync(0xffffffffu, hi0, s);
                    hi1 += __shfl_xor_sync(0xffffffffu, hi1, s);
                }
            }
            if (q == 0) {
                sm.racc[m0][ncol] += ls0; sm.racc[m1][ncol] += ls1;
                if (near) {
                    sm.rlo[m0][ncol] += lo0; sm.rlo[m1][ncol] += lo1;
                    sm.rhi[m0][ncol] += hi0; sm.rhi[m1][ncol] += hi1;
                } else if (diff < 0) {
                    sm.rlo[m0][ncol] += ls0; sm.rlo[m1][ncol] += ls1;
                } else {
                    sm.rhi[m0][ncol] += ls0; sm.rhi[m1][ncol] += ls1;
                }
            }
        }
        __syncthreads();

        // ---- P @ V mma ----
#pragma unroll
        for (int ks = 0; ks < 64; ks += 8) {
            unsigned a[4];
            a[0] = sm.Ptf[m0][ks + q];
            a[1] = sm.Ptf[m1][ks + q];
            a[2] = sm.Ptf[m0][ks + q + 4];
            a[3] = sm.Ptf[m1][ks + q + 4];
#pragma unroll
            for (int ni = 0; ni < 4; ni++) {
                unsigned bf[2];
                const int np = wn + (ni << 3) + g;
                bf[0] = sm.Vtf[ks + q][np];
                bf[1] = sm.Vtf[ks + q + 4][np];
                mma_tf32(oacc[ni], a, bf);
            }
        }
        __syncthreads();
    }

    // ---- epilogue ----
    if (tid < QT) {
        sm.lrowf[tid]       = sm.racc[tid][0] + sm.racc[tid][1];
        sm.bucket[tid][0]   = sm.rlo[tid][0] + sm.rlo[tid][1];
        sm.bucket[tid][64]  = sm.rhi[tid][0] + sm.rhi[tid][1];
    }
    __syncthreads();

#pragma unroll
    for (int it = 0; it < 16; it++) {
        const int e = tid + it * 256;
        const int r0 = e >> 6, c0 = e & 63;
        sm.Ptf[r0][c0] = f2tf(sm.bucket[r0][c0]);          // [q][r], r=0..63
        sm.Vtf[r0][c0] = f2tf(rel_emb_v[r0 * 64 + c0]);    // [r][d]
    }
    __syncthreads();
#pragma unroll
    for (int ks = 0; ks < 64; ks += 8) {
        unsigned a[4];
        a[0] = sm.Ptf[m0][ks + q];
        a[1] = sm.Ptf[m1][ks + q];
        a[2] = sm.Ptf[m0][ks + q + 4];
        a[3] = sm.Ptf[m1][ks + q + 4];
#pragma unroll
        for (int ni = 0; ni < 4; ni++) {
            unsigned bf[2];
            const int np = wn + (ni << 3) + g;
            bf[0] = sm.Vtf[ks + q][np];
            bf[1] = sm.Vtf[ks + q + 4][np];
            mma_tf32(oacc[ni], a, bf);
        }
    }
    {
        const float bw0 = sm.bucket[m0][64], bw1 = sm.bucket[m1][64];
        const float inv0 = 1.0f / sm.lrowf[m0], inv1 = 1.0f / sm.lrowf[m1];
#pragma unroll
        for (int ni = 0; ni < 4; ni++) {
            const int nl = wn + (ni << 3) + (q << 1);
            const float rv0 = rel_emb_v[64 * 64 + nl], rv1 = rel_emb_v[64 * 64 + nl + 1];
            float2 o0, o1;
            o0.x = (oacc[ni][0] + bw0 * rv0) * inv0;
            o0.y = (oacc[ni][1] + bw0 * rv1) * inv0;
            o1.x = (oacc[ni][2] + bw1 * rv0) * inv1;
            o1.y = (oacc[ni][3] + bw1 * rv1) * inv1;
            *(float2*)&g_ctx[(size_t)(b * L_ + qbase + m0) * DM_ + h * D_ + nl] = o0;
            *(float2*)&g_ctx[(size_t)(b * L_ + qbase + m1) * DM_ + h * D_ + nl] = o1;
        }
    }
}

// ============================ launch ============================
extern "C" void kernel_launch(void* const* d_in, const int* in_sizes, int n_in,
                              void* d_out, int out_size)
{
    const float* key        = (const float*)d_in[0];
    const float* value      = (const float*)d_in[1];
    const float* query      = (const float*)d_in[2];
    const unsigned char* mask = (const unsigned char*)d_in[3];
    const int*   rel_matrix = (const int*)d_in[4];
    const float* rel_mask   = (const float*)d_in[5];
    const float* Wk = (const float*)d_in[6];
    const float* bk = (const float*)d_in[7];
    const float* Wq = (const float*)d_in[8];
    const float* bq = (const float*)d_in[9];
    const float* Wv = (const float*)d_in[10];
    const float* bv = (const float*)d_in[11];
    const float* Wo = (const float*)d_in[12];
    const float* bo = (const float*)d_in[13];
    const float* rel_emb_k  = (const float*)d_in[14];
    const float* rel_emb_v  = (const float*)d_in[15];
    const float* tree_emb   = (const float*)d_in[16];

    static bool attr_set = false;
    if (!attr_set) {
        cudaFuncSetAttribute(attn_kernel, cudaFuncAttributeMaxDynamicSharedMemorySize,
                             (int)sizeof(AttnSmem));
        attr_set = true;
    }

    gemm_qkv<<<dim3(B_ * L_ / 128, DM_ / 64, 3), 256>>>(
        query, key, value, Wq, Wk, Wv, bq, bk, bv);

    attn_kernel<<<dim3(L_ / QT, H_, B_), 256, sizeof(AttnSmem)>>>(
        rel_matrix, rel_mask, mask, tree_emb, rel_emb_k, rel_emb_v);

    gemm_out<<<dim3(B_ * L_ / 128, DM_ / 64), 256>>>(Wo, bo, (float*)d_out);
}